// round 1
// baseline (speedup 1.0000x reference)
#include <cuda_runtime.h>
#include <math.h>

#define B_   16
#define E_   768
#define H_   12
#define HD_  64
#define N_   197
#define NP_  196
#define L_   12
#define FF_  3072
#define ROWS_ (B_*N_)          // 3152
#define SQRTE 27.712812921102035f

// ---------------- scratch (device globals; no allocation allowed) ----------
__device__ float g_h[ROWS_*E_];
__device__ float g_q[ROWS_*E_];
__device__ float g_k[ROWS_*E_];
__device__ float g_v[ROWS_*E_];
__device__ float g_a[ROWS_*E_];
__device__ float g_t[ROWS_*E_];
__device__ float g_u[ROWS_*FF_];
__device__ float g_g[ROWS_*FF_];

// ---------------- patch embed: one block per (b, patch) --------------------
__global__ void patch_embed(const float* __restrict__ x,
                            const float* __restrict__ pw,
                            const float* __restrict__ pb,
                            const float* __restrict__ pos,
                            float* __restrict__ h) {
    int bp = blockIdx.x;              // 0 .. B*196
    int b = bp / NP_, pidx = bp % NP_;
    int gi = pidx / 14, gj = pidx % 14;
    __shared__ float patch[768];
    for (int i = threadIdx.x; i < 768; i += blockDim.x) {
        int c  = i >> 8;              // channel
        int r  = i & 255;
        int ii = r >> 4, jj = r & 15;
        patch[i] = x[((b*3 + c)*224 + gi*16 + ii)*224 + gj*16 + jj];
    }
    __syncthreads();
    for (int e = threadIdx.x; e < E_; e += blockDim.x) {
        const float* w = pw + e*768;
        float acc = 0.f;
        #pragma unroll 8
        for (int i = 0; i < 768; i++) acc = fmaf(patch[i], w[i], acc);
        h[(b*N_ + 1 + pidx)*E_ + e] = acc + pb[e] + pos[(1 + pidx)*E_ + e];
    }
}

__global__ void cls_pos(const float* __restrict__ cls,
                        const float* __restrict__ pos,
                        float* __restrict__ h) {
    int b = blockIdx.x;
    for (int e = threadIdx.x; e < E_; e += blockDim.x)
        h[(b*N_)*E_ + e] = cls[e] + pos[e];
}

// ---------------- SGEMM: C[M,N] = A[M,K] * W[N,K]^T ------------------------
__global__ __launch_bounds__(256)
void sgemm_nt(const float* __restrict__ A, const float* __restrict__ W,
              float* __restrict__ C, int M, int N, int K) {
    __shared__ float As[64][17];
    __shared__ float Ws[64][17];
    const int tid = threadIdx.x;
    const int tx = tid & 15, ty = tid >> 4;
    const int row0 = blockIdx.y * 64, col0 = blockIdx.x * 64;
    float acc[4][4] = {};
    for (int k0 = 0; k0 < K; k0 += 16) {
        #pragma unroll
        for (int t = 0; t < 4; t++) {
            int i = tid + t*256;
            int r = i >> 4, c = i & 15;
            int gr = row0 + r;
            As[r][c] = (gr < M) ? A[gr*K + k0 + c] : 0.f;
            Ws[r][c] = W[(col0 + r)*K + k0 + c];     // N is a multiple of 64
        }
        __syncthreads();
        #pragma unroll
        for (int kk = 0; kk < 16; kk++) {
            float a[4], b[4];
            #pragma unroll
            for (int i = 0; i < 4; i++) a[i] = As[ty*4 + i][kk];
            #pragma unroll
            for (int j = 0; j < 4; j++) b[j] = Ws[tx*4 + j][kk];
            #pragma unroll
            for (int i = 0; i < 4; i++)
                #pragma unroll
                for (int j = 0; j < 4; j++)
                    acc[i][j] = fmaf(a[i], b[j], acc[i][j]);
        }
        __syncthreads();
    }
    #pragma unroll
    for (int i = 0; i < 4; i++) {
        int gr = row0 + ty*4 + i;
        if (gr < M) {
            #pragma unroll
            for (int j = 0; j < 4; j++)
                C[gr*N + col0 + tx*4 + j] = acc[i][j];
        }
    }
}

// ---------------- per-head cosine-norm + scale for q/k ---------------------
__global__ void qk_ns(float* __restrict__ q, const float* __restrict__ s) {
    int idx = blockIdx.x;             // rows * H
    int h = idx % H_;
    int row = idx / H_;
    float* p = q + row*E_ + h*HD_;
    int d = threadIdx.x;              // 64 threads
    float v = p[d];
    float ss = v*v;
    #pragma unroll
    for (int o = 16; o > 0; o >>= 1) ss += __shfl_xor_sync(0xffffffffu, ss, o);
    __shared__ float w2[2];
    if ((d & 31) == 0) w2[d >> 5] = ss;
    __syncthreads();
    float nrm = sqrtf(w2[0] + w2[1]);
    p[d] = v / fmaxf(nrm, 1e-6f) * (s[h*HD_ + d] * SQRTE);
}

// ---------------- attention: one block per (b, h, query) -------------------
__global__ __launch_bounds__(256)
void attn(const float* __restrict__ q, const float* __restrict__ k,
          const float* __restrict__ v, float* __restrict__ o) {
    int idx = blockIdx.x;
    int qn = idx % N_; idx /= N_;
    int h = idx % H_;
    int b = idx / H_;
    const int base = (b*N_)*E_ + h*HD_;
    __shared__ float qs[HD_];
    __shared__ float lg[N_];
    __shared__ float red[256];
    int tid = threadIdx.x;
    if (tid < HD_) qs[tid] = q[base + qn*E_ + tid];
    __syncthreads();
    for (int m = tid; m < N_; m += 256) {
        const float* kr = k + base + m*E_;
        float s = 0.f;
        #pragma unroll
        for (int d = 0; d < HD_; d++) s = fmaf(qs[d], kr[d], s);
        lg[m] = s * 8.0f;                       // * sqrt(HD)
    }
    __syncthreads();
    float mx = -1e30f;
    for (int m = tid; m < N_; m += 256) mx = fmaxf(mx, lg[m]);
    red[tid] = mx; __syncthreads();
    for (int s = 128; s > 0; s >>= 1) {
        if (tid < s) red[tid] = fmaxf(red[tid], red[tid + s]);
        __syncthreads();
    }
    mx = red[0]; __syncthreads();
    float sm = 0.f;
    for (int m = tid; m < N_; m += 256) {
        float p = expf(lg[m] - mx);
        lg[m] = p; sm += p;
    }
    red[tid] = sm; __syncthreads();
    for (int s = 128; s > 0; s >>= 1) {
        if (tid < s) red[tid] += red[tid + s];
        __syncthreads();
    }
    float inv = 1.0f / red[0];
    if (tid < HD_) {
        float acc = 0.f;
        for (int m = 0; m < N_; m++)
            acc = fmaf(lg[m], v[base + m*E_ + tid], acc);
        o[base + qn*E_ + tid] = acc * inv;
    }
}

// ---------------- residual + double cosine-norm -----------------------------
__global__ __launch_bounds__(256)
void res_cn(float* __restrict__ h, const float* __restrict__ d,
            const float* __restrict__ alpha) {
    int row = blockIdx.x;
    int tid = threadIdx.x;
    const float* dr = d + row*E_;
    float* hr = h + row*E_;
    __shared__ float red[256];
    float dv[3], hv[3];
    float ss = 0.f;
    #pragma unroll
    for (int t = 0; t < 3; t++) {
        int e = tid + t*256;
        dv[t] = dr[e]; hv[t] = hr[e];
        ss += dv[t]*dv[t];
    }
    red[tid] = ss; __syncthreads();
    for (int s = 128; s > 0; s >>= 1) {
        if (tid < s) red[tid] += red[tid + s];
        __syncthreads();
    }
    float inv1 = 1.0f / fmaxf(sqrtf(red[0]), 1e-6f);
    __syncthreads();
    float y[3]; float ss2 = 0.f;
    #pragma unroll
    for (int t = 0; t < 3; t++) {
        int e = tid + t*256;
        float a = alpha[e] * (0.05f * SQRTE);
        y[t] = hv[t] + a*(dv[t]*inv1 - hv[t]);
        ss2 += y[t]*y[t];
    }
    red[tid] = ss2; __syncthreads();
    for (int s = 128; s > 0; s >>= 1) {
        if (tid < s) red[tid] += red[tid + s];
        __syncthreads();
    }
    float inv2 = 1.0f / fmaxf(sqrtf(red[0]), 1e-6f);
    #pragma unroll
    for (int t = 0; t < 3; t++) hr[tid + t*256] = y[t]*inv2;
}

// ---------------- MLP activation: u *= s_u; gated silu ----------------------
__global__ void mlp_act(float* __restrict__ u, const float* __restrict__ g,
                        const float* __restrict__ s_u, const float* __restrict__ s_v) {
    int i = blockIdx.x*blockDim.x + threadIdx.x;
    if (i >= ROWS_*FF_) return;
    int j = i % FF_;
    float uu = u[i]*s_u[j];
    float vv = g[i]*s_v[j]*SQRTE;
    float sig = 1.0f/(1.0f + expf(-vv));
    u[i] = uu*vv*sig;
}

// ---------------- LayerNorm tap -> output (drop CLS token) ------------------
__global__ __launch_bounds__(256)
void ln_out(const float* __restrict__ h, const float* __restrict__ w,
            const float* __restrict__ b, float* __restrict__ o) {
    int br = blockIdx.x;               // B*196
    int bb = br / NP_, n = br % NP_ + 1;
    const float* hr = h + (bb*N_ + n)*E_;
    float* orow = o + br*E_;
    __shared__ float red[256];
    int tid = threadIdx.x;
    float vv[3];
    float s = 0.f;
    #pragma unroll
    for (int t = 0; t < 3; t++) { vv[t] = hr[tid + t*256]; s += vv[t]; }
    red[tid] = s; __syncthreads();
    for (int st = 128; st > 0; st >>= 1) {
        if (tid < st) red[tid] += red[tid + st];
        __syncthreads();
    }
    float mean = red[0] * (1.0f/E_);
    __syncthreads();
    float s2 = 0.f;
    #pragma unroll
    for (int t = 0; t < 3; t++) { float dd = vv[t] - mean; s2 += dd*dd; }
    red[tid] = s2; __syncthreads();
    for (int st = 128; st > 0; st >>= 1) {
        if (tid < st) red[tid] += red[tid + st];
        __syncthreads();
    }
    float inv = rsqrtf(red[0]*(1.0f/E_) + 1e-6f);
    #pragma unroll
    for (int t = 0; t < 3; t++) {
        int e = tid + t*256;
        orow[e] = (vv[t] - mean)*inv*w[e] + b[e];
    }
}

// ---------------- driver -----------------------------------------------------
extern "C" void kernel_launch(void* const* d_in, const int* in_sizes, int n_in,
                              void* d_out, int out_size) {
    (void)in_sizes; (void)n_in; (void)out_size;
    const float* x       = (const float*)d_in[0];
    const float* patch_w = (const float*)d_in[1];
    const float* patch_b = (const float*)d_in[2];
    const float* cls     = (const float*)d_in[3];
    const float* pos     = (const float*)d_in[4];
    const float* Wq      = (const float*)d_in[5];
    const float* Wk      = (const float*)d_in[6];
    const float* Wv      = (const float*)d_in[7];
    const float* Wo      = (const float*)d_in[8];
    const float* s_qk    = (const float*)d_in[9];
    const float* Wup     = (const float*)d_in[10];
    const float* Wgate   = (const float*)d_in[11];
    const float* Wdown   = (const float*)d_in[12];
    const float* s_u     = (const float*)d_in[13];
    const float* s_v     = (const float*)d_in[14];
    const float* aA      = (const float*)d_in[15];
    const float* aM      = (const float*)d_in[16];
    const float* fcw     = (const float*)d_in[17];
    const float* fcb     = (const float*)d_in[18];
    float* out = (float*)d_out;

    float *h, *q, *k, *v, *a, *t, *u, *g;
    cudaGetSymbolAddress((void**)&h, g_h);
    cudaGetSymbolAddress((void**)&q, g_q);
    cudaGetSymbolAddress((void**)&k, g_k);
    cudaGetSymbolAddress((void**)&v, g_v);
    cudaGetSymbolAddress((void**)&a, g_a);
    cudaGetSymbolAddress((void**)&t, g_t);
    cudaGetSymbolAddress((void**)&u, g_u);
    cudaGetSymbolAddress((void**)&g, g_g);

    patch_embed<<<B_*NP_, 256>>>(x, patch_w, patch_b, pos, h);
    cls_pos<<<B_, 256>>>(cls, pos, h);

    dim3 grE((E_ + 63)/64, (ROWS_ + 63)/64);
    dim3 grF((FF_ + 63)/64, (ROWS_ + 63)/64);

    for (int l = 0; l < L_; l++) {
        sgemm_nt<<<grE, 256>>>(h, Wq + (size_t)l*E_*E_, q, ROWS_, E_, E_);
        sgemm_nt<<<grE, 256>>>(h, Wk + (size_t)l*E_*E_, k, ROWS_, E_, E_);
        sgemm_nt<<<grE, 256>>>(h, Wv + (size_t)l*E_*E_, v, ROWS_, E_, E_);
        qk_ns<<<ROWS_*H_, HD_>>>(q, s_qk + (size_t)l*H_*HD_);
        qk_ns<<<ROWS_*H_, HD_>>>(k, s_qk + (size_t)l*H_*HD_);
        attn<<<B_*H_*N_, 256>>>(q, k, v, a);
        sgemm_nt<<<grE, 256>>>(a, Wo + (size_t)l*E_*E_, t, ROWS_, E_, E_);
        res_cn<<<ROWS_, 256>>>(h, t, aA + (size_t)l*E_);
        sgemm_nt<<<grF, 256>>>(h, Wup + (size_t)l*FF_*E_, u, ROWS_, FF_, E_);
        sgemm_nt<<<grF, 256>>>(h, Wgate + (size_t)l*FF_*E_, g, ROWS_, FF_, E_);
        mlp_act<<<(ROWS_*FF_ + 255)/256, 256>>>(u, g, s_u + (size_t)l*FF_, s_v + (size_t)l*FF_);
        sgemm_nt<<<grE, 256>>>(u, Wdown + (size_t)l*E_*FF_, t, ROWS_, E_, FF_);
        res_cn<<<ROWS_, 256>>>(h, t, aM + (size_t)l*E_);
        if (l == L_ - 2)
            ln_out<<<B_*NP_, 256>>>(h, fcw, fcb, out);
    }
    ln_out<<<B_*NP_, 256>>>(h, fcw, fcb, out + (size_t)B_*NP_*E_);
}

// round 3
// speedup vs baseline: 1.6053x; 1.6053x over previous
#include <cuda_runtime.h>
#include <cuda_bf16.h>
#include <math.h>
#include <stdint.h>

#define B_   16
#define E_   768
#define H_   12
#define HD_  64
#define N_   197
#define NP_  196
#define L_   12
#define FF_  3072
#define ROWS_ (B_*N_)          // 3152
#define SQRTE 27.712812921102035f

// weight family sizes/offsets (elements) inside the packed bf16 weight buffers
#define NQ_   (L_*E_*E_)
#define NUP_  (L_*FF_*E_)
#define OFF_Q    0
#define OFF_K    (NQ_)
#define OFF_V    (2*NQ_)
#define OFF_O    (3*NQ_)
#define OFF_UP   (4*NQ_)
#define OFF_GATE (4*NQ_ + NUP_)
#define OFF_DOWN (4*NQ_ + 2*NUP_)
#define WTOT_    (4*NQ_ + 3*NUP_)

// ---------------- scratch (device globals; no allocation allowed) ----------
__device__ float g_h[ROWS_*E_];
__device__ float g_q[ROWS_*E_];
__device__ float g_k[ROWS_*E_];
__device__ float g_v[ROWS_*E_];
__device__ float g_a[ROWS_*E_];
__device__ float g_t[ROWS_*E_];
__device__ float g_u[ROWS_*FF_];
__device__ float g_g[ROWS_*FF_];
__device__ __nv_bfloat16 g_act_hi[ROWS_*FF_];
__device__ __nv_bfloat16 g_act_lo[ROWS_*FF_];
__device__ __nv_bfloat16 g_w_hi[WTOT_];
__device__ __nv_bfloat16 g_w_lo[WTOT_];

// ======================= mma.sync GEMM ======================================
// C[M,N] = A[M,K] * W[N,K]^T ; A,W in bf16 hi/lo pairs, fp32 accum.
// D = Ah*Wh + Ah*Wl + Al*Wh
#define BM 128
#define BN 128
#define BK 32
#define PADE 40                       // smem row stride, elements (80 B)
#define ARR_BYTES (128*PADE*2)        // 10240
#define STAGE_BYTES (4*ARR_BYTES)     // 40960
#define GSMEM (2*STAGE_BYTES)         // 81920

__device__ __forceinline__ uint32_t smem_u32(const void* p) {
    uint32_t a;
    asm("{ .reg .u64 t; cvta.to.shared.u64 t, %1; cvt.u32.u64 %0, t; }"
        : "=r"(a) : "l"(p));
    return a;
}
__device__ __forceinline__ void cp16(uint32_t dst, const void* src) {
    asm volatile("cp.async.cg.shared.global [%0], [%1], 16;"
                 :: "r"(dst), "l"(src) : "memory");
}
#define CP_COMMIT() asm volatile("cp.async.commit_group;" ::: "memory")
#define CP_WAIT1()  asm volatile("cp.async.wait_group 1;" ::: "memory")
#define CP_WAIT0()  asm volatile("cp.async.wait_group 0;" ::: "memory")

#define LDSM4(r, addr) \
    asm volatile("ldmatrix.sync.aligned.m8n8.x4.shared.b16 {%0,%1,%2,%3}, [%4];" \
        : "=r"((r)[0]), "=r"((r)[1]), "=r"((r)[2]), "=r"((r)[3]) : "r"(addr))
#define LDSM2(r, addr) \
    asm volatile("ldmatrix.sync.aligned.m8n8.x2.shared.b16 {%0,%1}, [%2];" \
        : "=r"((r)[0]), "=r"((r)[1]) : "r"(addr))
#define MMA_BF16(d, a, b) \
    asm volatile("mma.sync.aligned.m16n8k16.row.col.f32.bf16.bf16.f32 " \
        "{%0,%1,%2,%3}, {%4,%5,%6,%7}, {%8,%9}, {%0,%1,%2,%3};" \
        : "+f"((d)[0]), "+f"((d)[1]), "+f"((d)[2]), "+f"((d)[3]) \
        : "r"((a)[0]), "r"((a)[1]), "r"((a)[2]), "r"((a)[3]), \
          "r"((b)[0]), "r"((b)[1]))

__device__ __forceinline__ void load_stage(
        uint32_t sbase,
        const __nv_bfloat16* __restrict__ Ah, const __nv_bfloat16* __restrict__ Al,
        const __nv_bfloat16* __restrict__ Wh, const __nv_bfloat16* __restrict__ Wl,
        int m0, int n0, int k0, int M, int K, int tid) {
    #pragma unroll
    for (int i = 0; i < 8; i++) {
        int idx = tid + i*256;
        int arr = idx >> 9;
        int rem = idx & 511;
        int row = rem >> 2;
        int seg = rem & 3;
        uint32_t dst = sbase + arr*ARR_BYTES + row*(PADE*2) + seg*16;
        const __nv_bfloat16* src;
        if (arr == 0)      { int r = m0 + row; if (r >= M) r = M - 1;
                             src = Ah + (size_t)r*K + k0 + seg*8; }
        else if (arr == 1) { int r = m0 + row; if (r >= M) r = M - 1;
                             src = Al + (size_t)r*K + k0 + seg*8; }
        else if (arr == 2) { src = Wh + (size_t)(n0 + row)*K + k0 + seg*8; }
        else               { src = Wl + (size_t)(n0 + row)*K + k0 + seg*8; }
        cp16(dst, src);
    }
}

__global__ __launch_bounds__(256)
void gemm_mma(const __nv_bfloat16* __restrict__ Ah,
              const __nv_bfloat16* __restrict__ Al,
              const __nv_bfloat16* __restrict__ Wh,
              const __nv_bfloat16* __restrict__ Wl,
              float* __restrict__ C, int M, int N, int K) {
    extern __shared__ char smem[];
    const uint32_t sb = smem_u32(smem);
    const int tid = threadIdx.x;
    const int lane = tid & 31, wid = tid >> 5;
    const int wm = (wid & 1) * 64;        // warp m-offset inside CTA tile
    const int wn = (wid >> 1) * 32;       // warp n-offset
    const int m0 = blockIdx.y * BM, n0 = blockIdx.x * BN;

    float acc[4][4][4] = {};

    const int ntiles = K / BK;
    load_stage(sb, Ah, Al, Wh, Wl, m0, n0, 0, M, K, tid);
    CP_COMMIT();

    const int arow = lane & 15, acolsel = (lane >> 4) * 8;
    const int brow = lane & 7,  bcolsel = ((lane >> 3) & 1) * 8;

    for (int t = 0; t < ntiles; t++) {
        uint32_t sbase = sb + (t & 1) * STAGE_BYTES;
        if (t + 1 < ntiles) {
            load_stage(sb + ((t + 1) & 1) * STAGE_BYTES,
                       Ah, Al, Wh, Wl, m0, n0, (t + 1) * BK, M, K, tid);
            CP_COMMIT();
            CP_WAIT1();
        } else {
            CP_WAIT0();
        }
        __syncthreads();

        const uint32_t sA_h = sbase;
        const uint32_t sA_l = sbase + ARR_BYTES;
        const uint32_t sW_h = sbase + 2*ARR_BYTES;
        const uint32_t sW_l = sbase + 3*ARR_BYTES;

        #pragma unroll
        for (int ks = 0; ks < 2; ks++) {
            const int kb = ks * 16;
            uint32_t ah[4][4], al[4][4], bh[4][2], bl[4][2];
            #pragma unroll
            for (int mt = 0; mt < 4; mt++) {
                uint32_t off = (wm + mt*16 + arow)*(PADE*2) + (kb + acolsel)*2;
                LDSM4(ah[mt], sA_h + off);
                LDSM4(al[mt], sA_l + off);
            }
            #pragma unroll
            for (int nt = 0; nt < 4; nt++) {
                uint32_t off = (wn + nt*8 + brow)*(PADE*2) + (kb + bcolsel)*2;
                LDSM2(bh[nt], sW_h + off);
                LDSM2(bl[nt], sW_l + off);
            }
            #pragma unroll
            for (int mt = 0; mt < 4; mt++)
                #pragma unroll
                for (int nt = 0; nt < 4; nt++) {
                    MMA_BF16(acc[mt][nt], ah[mt], bh[nt]);
                    MMA_BF16(acc[mt][nt], ah[mt], bl[nt]);
                    MMA_BF16(acc[mt][nt], al[mt], bh[nt]);
                }
        }
        __syncthreads();
    }

    // epilogue
    #pragma unroll
    for (int mt = 0; mt < 4; mt++) {
        int rbase = m0 + wm + mt*16 + (lane >> 2);
        #pragma unroll
        for (int half = 0; half < 2; half++) {
            int r = rbase + half*8;
            if (r < M) {
                float* crow = C + (size_t)r*N + n0 + wn + (lane & 3)*2;
                #pragma unroll
                for (int nt = 0; nt < 4; nt++) {
                    float2 v = make_float2(acc[mt][nt][half*2],
                                           acc[mt][nt][half*2 + 1]);
                    *reinterpret_cast<float2*>(crow + nt*8) = v;
                }
            }
        }
    }
}

// ---------------- fp32 -> bf16 hi/lo split ----------------------------------
__global__ void cvt_split(const float* __restrict__ src,
                          __nv_bfloat16* __restrict__ hi,
                          __nv_bfloat16* __restrict__ lo, int n) {
    int i = blockIdx.x * blockDim.x + threadIdx.x;
    if (i >= n) return;
    float x = src[i];
    __nv_bfloat16 h = __float2bfloat16(x);
    hi[i] = h;
    lo[i] = __float2bfloat16(x - __bfloat162float(h));
}

// ---------------- patch embed -----------------------------------------------
__global__ void patch_embed(const float* __restrict__ x,
                            const float* __restrict__ pw,
                            const float* __restrict__ pb,
                            const float* __restrict__ pos,
                            float* __restrict__ h) {
    int bp = blockIdx.x;
    int b = bp / NP_, pidx = bp % NP_;
    int gi = pidx / 14, gj = pidx % 14;
    __shared__ float patch[768];
    for (int i = threadIdx.x; i < 768; i += blockDim.x) {
        int c  = i >> 8;
        int r  = i & 255;
        int ii = r >> 4, jj = r & 15;
        patch[i] = x[((b*3 + c)*224 + gi*16 + ii)*224 + gj*16 + jj];
    }
    __syncthreads();
    for (int e = threadIdx.x; e < E_; e += blockDim.x) {
        const float* w = pw + e*768;
        float acc = 0.f;
        #pragma unroll 8
        for (int i = 0; i < 768; i++) acc = fmaf(patch[i], w[i], acc);
        h[(b*N_ + 1 + pidx)*E_ + e] = acc + pb[e] + pos[(1 + pidx)*E_ + e];
    }
}

__global__ void cls_pos(const float* __restrict__ cls,
                        const float* __restrict__ pos,
                        float* __restrict__ h) {
    int b = blockIdx.x;
    for (int e = threadIdx.x; e < E_; e += blockDim.x)
        h[(b*N_)*E_ + e] = cls[e] + pos[e];
}

// ---------------- per-head cosine-norm + scale for q/k -----------------------
__global__ void qk_ns(float* __restrict__ q, const float* __restrict__ s) {
    int idx = blockIdx.x;
    int h = idx % H_;
    int row = idx / H_;
    float* p = q + row*E_ + h*HD_;
    int d = threadIdx.x;
    float v = p[d];
    float ss = v*v;
    #pragma unroll
    for (int o = 16; o > 0; o >>= 1) ss += __shfl_xor_sync(0xffffffffu, ss, o);
    __shared__ float w2[2];
    if ((d & 31) == 0) w2[d >> 5] = ss;
    __syncthreads();
    float nrm = sqrtf(w2[0] + w2[1]);
    p[d] = v / fmaxf(nrm, 1e-6f) * (s[h*HD_ + d] * SQRTE);
}

// ---------------- attention: one block per (b, h, query) ---------------------
__global__ __launch_bounds__(256)
void attn(const float* __restrict__ q, const float* __restrict__ k,
          const float* __restrict__ v, float* __restrict__ o) {
    int idx = blockIdx.x;
    int qn = idx % N_; idx /= N_;
    int h = idx % H_;
    int b = idx / H_;
    const int base = (b*N_)*E_ + h*HD_;
    __shared__ float qs[HD_];
    __shared__ float lg[N_];
    __shared__ float red[256];
    __shared__ float acc4[4][HD_];
    int tid = threadIdx.x;
    if (tid < HD_) qs[tid] = q[base + qn*E_ + tid];
    __syncthreads();
    for (int m = tid; m < N_; m += 256) {
        const float* kr = k + base + m*E_;
        float s = 0.f;
        #pragma unroll
        for (int d = 0; d < HD_; d++) s = fmaf(qs[d], kr[d], s);
        lg[m] = s * 8.0f;
    }
    __syncthreads();
    float mx = -1e30f;
    for (int m = tid; m < N_; m += 256) mx = fmaxf(mx, lg[m]);
    red[tid] = mx; __syncthreads();
    for (int s = 128; s > 0; s >>= 1) {
        if (tid < s) red[tid] = fmaxf(red[tid], red[tid + s]);
        __syncthreads();
    }
    mx = red[0]; __syncthreads();
    float sm = 0.f;
    for (int m = tid; m < N_; m += 256) {
        float p = expf(lg[m] - mx);
        lg[m] = p; sm += p;
    }
    red[tid] = sm; __syncthreads();
    for (int s = 128; s > 0; s >>= 1) {
        if (tid < s) red[tid] += red[tid + s];
        __syncthreads();
    }
    int d = tid & 63, c = tid >> 6;
    float acc = 0.f;
    for (int m = c; m < N_; m += 4)
        acc = fmaf(lg[m], v[base + m*E_ + d], acc);
    acc4[c][d] = acc;
    __syncthreads();
    if (tid < HD_) {
        float inv = 1.0f / red[0];
        o[base + qn*E_ + tid] =
            (acc4[0][tid] + acc4[1][tid] + acc4[2][tid] + acc4[3][tid]) * inv;
    }
}

// ---------------- residual + double cosine-norm -------------------------------
__global__ __launch_bounds__(256)
void res_cn(float* __restrict__ h, const float* __restrict__ d,
            const float* __restrict__ alpha) {
    int row = blockIdx.x;
    int tid = threadIdx.x;
    const float* dr = d + row*E_;
    float* hr = h + row*E_;
    __shared__ float red[256];
    float dv[3], hv[3];
    float ss = 0.f;
    #pragma unroll
    for (int t = 0; t < 3; t++) {
        int e = tid + t*256;
        dv[t] = dr[e]; hv[t] = hr[e];
        ss += dv[t]*dv[t];
    }
    red[tid] = ss; __syncthreads();
    for (int s = 128; s > 0; s >>= 1) {
        if (tid < s) red[tid] += red[tid + s];
        __syncthreads();
    }
    float inv1 = 1.0f / fmaxf(sqrtf(red[0]), 1e-6f);
    __syncthreads();
    float y[3]; float ss2 = 0.f;
    #pragma unroll
    for (int t = 0; t < 3; t++) {
        int e = tid + t*256;
        float a = alpha[e] * (0.05f * SQRTE);
        y[t] = hv[t] + a*(dv[t]*inv1 - hv[t]);
        ss2 += y[t]*y[t];
    }
    red[tid] = ss2; __syncthreads();
    for (int s = 128; s > 0; s >>= 1) {
        if (tid < s) red[tid] += red[tid + s];
        __syncthreads();
    }
    float inv2 = 1.0f / fmaxf(sqrtf(red[0]), 1e-6f);
    #pragma unroll
    for (int t = 0; t < 3; t++) hr[tid + t*256] = y[t]*inv2;
}

// ---------------- MLP activation ---------------------------------------------
__global__ void mlp_act(float* __restrict__ u, const float* __restrict__ g,
                        const float* __restrict__ s_u, const float* __restrict__ s_v) {
    int i = blockIdx.x*blockDim.x + threadIdx.x;
    if (i >= ROWS_*FF_) return;
    int j = i % FF_;
    float uu = u[i]*s_u[j];
    float vv = g[i]*s_v[j]*SQRTE;
    float sig = 1.0f/(1.0f + expf(-vv));
    u[i] = uu*vv*sig;
}

// ---------------- LayerNorm tap -> output (drop CLS token) --------------------
__global__ __launch_bounds__(256)
void ln_out(const float* __restrict__ h, const float* __restrict__ w,
            const float* __restrict__ b, float* __restrict__ o) {
    int br = blockIdx.x;
    int bb = br / NP_, n = br % NP_ + 1;
    const float* hr = h + (bb*N_ + n)*E_;
    float* orow = o + br*E_;
    __shared__ float red[256];
    int tid = threadIdx.x;
    float vv[3];
    float s = 0.f;
    #pragma unroll
    for (int t = 0; t < 3; t++) { vv[t] = hr[tid + t*256]; s += vv[t]; }
    red[tid] = s; __syncthreads();
    for (int st = 128; st > 0; st >>= 1) {
        if (tid < st) red[tid] += red[tid + st];
        __syncthreads();
    }
    float mean = red[0] * (1.0f/E_);
    __syncthreads();
    float s2 = 0.f;
    #pragma unroll
    for (int t = 0; t < 3; t++) { float dd = vv[t] - mean; s2 += dd*dd; }
    red[tid] = s2; __syncthreads();
    for (int st = 128; st > 0; st >>= 1) {
        if (tid < st) red[tid] += red[tid + st];
        __syncthreads();
    }
    float inv = rsqrtf(red[0]*(1.0f/E_) + 1e-6f);
    #pragma unroll
    for (int t = 0; t < 3; t++) {
        int e = tid + t*256;
        orow[e] = (vv[t] - mean)*inv*w[e] + b[e];
    }
}

// ======================= driver ==============================================
extern "C" void kernel_launch(void* const* d_in, const int* in_sizes, int n_in,
                              void* d_out, int out_size) {
    (void)in_sizes; (void)n_in; (void)out_size;
    const float* x       = (const float*)d_in[0];
    const float* patch_w = (const float*)d_in[1];
    const float* patch_b = (const float*)d_in[2];
    const float* cls     = (const float*)d_in[3];
    const float* pos     = (const float*)d_in[4];
    const float* Wq      = (const float*)d_in[5];
    const float* Wk      = (const float*)d_in[6];
    const float* Wv      = (const float*)d_in[7];
    const float* Wo      = (const float*)d_in[8];
    const float* s_qk    = (const float*)d_in[9];
    const float* Wup     = (const float*)d_in[10];
    const float* Wgate   = (const float*)d_in[11];
    const float* Wdown   = (const float*)d_in[12];
    const float* s_u     = (const float*)d_in[13];
    const float* s_v     = (const float*)d_in[14];
    const float* aA      = (const float*)d_in[15];
    const float* aM      = (const float*)d_in[16];
    const float* fcw     = (const float*)d_in[17];
    const float* fcb     = (const float*)d_in[18];
    float* out = (float*)d_out;

    float *h, *q, *k, *v, *a, *t, *u, *g;
    __nv_bfloat16 *ah, *al, *wh, *wl;
    cudaGetSymbolAddress((void**)&h, g_h);
    cudaGetSymbolAddress((void**)&q, g_q);
    cudaGetSymbolAddress((void**)&k, g_k);
    cudaGetSymbolAddress((void**)&v, g_v);
    cudaGetSymbolAddress((void**)&a, g_a);
    cudaGetSymbolAddress((void**)&t, g_t);
    cudaGetSymbolAddress((void**)&u, g_u);
    cudaGetSymbolAddress((void**)&g, g_g);
    cudaGetSymbolAddress((void**)&ah, g_act_hi);
    cudaGetSymbolAddress((void**)&al, g_act_lo);
    cudaGetSymbolAddress((void**)&wh, g_w_hi);
    cudaGetSymbolAddress((void**)&wl, g_w_lo);

    cudaFuncSetAttribute(gemm_mma, cudaFuncAttributeMaxDynamicSharedMemorySize,
                         GSMEM);

    // weight split fp32 -> bf16 hi/lo (every call; deterministic)
    cvt_split<<<(NQ_ + 255)/256, 256>>>(Wq,    wh + OFF_Q,    wl + OFF_Q,    NQ_);
    cvt_split<<<(NQ_ + 255)/256, 256>>>(Wk,    wh + OFF_K,    wl + OFF_K,    NQ_);
    cvt_split<<<(NQ_ + 255)/256, 256>>>(Wv,    wh + OFF_V,    wl + OFF_V,    NQ_);
    cvt_split<<<(NQ_ + 255)/256, 256>>>(Wo,    wh + OFF_O,    wl + OFF_O,    NQ_);
    cvt_split<<<(NUP_ + 255)/256, 256>>>(Wup,   wh + OFF_UP,   wl + OFF_UP,   NUP_);
    cvt_split<<<(NUP_ + 255)/256, 256>>>(Wgate, wh + OFF_GATE, wl + OFF_GATE, NUP_);
    cvt_split<<<(NUP_ + 255)/256, 256>>>(Wdown, wh + OFF_DOWN, wl + OFF_DOWN, NUP_);

    patch_embed<<<B_*NP_, 256>>>(x, patch_w, patch_b, pos, h);
    cls_pos<<<B_, 256>>>(cls, pos, h);

    dim3 gE(E_/BN, (ROWS_ + BM - 1)/BM);    // (6, 25)
    dim3 gF(FF_/BN, (ROWS_ + BM - 1)/BM);   // (24, 25)
    const int nE = ROWS_*E_, nF = ROWS_*FF_;

    for (int l = 0; l < L_; l++) {
        const size_t oq = (size_t)l*E_*E_;
        const size_t of = (size_t)l*FF_*E_;
        cvt_split<<<(nE + 255)/256, 256>>>(h, ah, al, nE);
        gemm_mma<<<gE, 256, GSMEM>>>(ah, al, wh+OFF_Q+oq,  wl+OFF_Q+oq,  q, ROWS_, E_, E_);
        gemm_mma<<<gE, 256, GSMEM>>>(ah, al, wh+OFF_K+oq,  wl+OFF_K+oq,  k, ROWS_, E_, E_);
        gemm_mma<<<gE, 256, GSMEM>>>(ah, al, wh+OFF_V+oq,  wl+OFF_V+oq,  v, ROWS_, E_, E_);
        qk_ns<<<ROWS_*H_, HD_>>>(q, s_qk + (size_t)l*H_*HD_);
        qk_ns<<<ROWS_*H_, HD_>>>(k, s_qk + (size_t)l*H_*HD_);
        attn<<<B_*H_*N_, 256>>>(q, k, v, a);
        cvt_split<<<(nE + 255)/256, 256>>>(a, ah, al, nE);
        gemm_mma<<<gE, 256, GSMEM>>>(ah, al, wh+OFF_O+oq,  wl+OFF_O+oq,  t, ROWS_, E_, E_);
        res_cn<<<ROWS_, 256>>>(h, t, aA + (size_t)l*E_);
        cvt_split<<<(nE + 255)/256, 256>>>(h, ah, al, nE);
        gemm_mma<<<gF, 256, GSMEM>>>(ah, al, wh+OFF_UP+of,   wl+OFF_UP+of,   u, ROWS_, FF_, E_);
        gemm_mma<<<gF, 256, GSMEM>>>(ah, al, wh+OFF_GATE+of, wl+OFF_GATE+of, g, ROWS_, FF_, E_);
        mlp_act<<<(nF + 255)/256, 256>>>(u, g, s_u + (size_t)l*FF_, s_v + (size_t)l*FF_);
        cvt_split<<<(nF + 255)/256, 256>>>(u, ah, al, nF);
        gemm_mma<<<gE, 256, GSMEM>>>(ah, al, wh+OFF_DOWN+of, wl+OFF_DOWN+of, t, ROWS_, E_, FF_);
        res_cn<<<ROWS_, 256>>>(h, t, aM + (size_t)l*E_);
        if (l == L_ - 2)
            ln_out<<<B_*NP_, 256>>>(h, fcw, fcb, out);
    }
    ln_out<<<B_*NP_, 256>>>(h, fcw, fcb, out + (size_t)B_*NP_*E_);
}

// round 4
// speedup vs baseline: 3.0547x; 1.9029x over previous
#include <cuda_runtime.h>
#include <cuda_bf16.h>
#include <math.h>
#include <stdint.h>

#define B_   16
#define E_   768
#define H_   12
#define HD_  64
#define N_   197
#define NP_  196
#define L_   12
#define FF_  3072
#define ROWS_ (B_*N_)          // 3152
#define SQRTE 27.712812921102035f
#define EE_   (E_*E_)
#define FFE_  (FF_*E_)

// packed bf16 weight layout: [QKV(3*NQ)] [O(NQ)] [UPGATE(2*NUP)] [DOWN(NUP)]
#define NQ_   (L_*EE_)
#define NUP_  (L_*FFE_)
#define OFF_QKV  0
#define OFF_O    (3*NQ_)
#define OFF_UG   (4*NQ_)
#define OFF_DOWN (4*NQ_ + 2*NUP_)
#define WTOT_    (4*NQ_ + 3*NUP_)

// ---------------- scratch (device globals; no allocation allowed) ----------
__device__ float g_h[ROWS_*E_];
__device__ float g_t[ROWS_*E_];
__device__ float g_qkv[ROWS_*3*E_];
__device__ float g_ug[ROWS_*2*FF_];
__device__ __nv_bfloat16 g_act_hi[ROWS_*FF_];
__device__ __nv_bfloat16 g_act_lo[ROWS_*FF_];
__device__ __nv_bfloat16 g_w_hi[WTOT_];
__device__ __nv_bfloat16 g_w_lo[WTOT_];

// ======================= mma.sync GEMM ======================================
// C[M,N] = A[M,K] * W[N,K]^T ; A,W bf16 hi/lo pairs, fp32 accum.
// D = Ah*Wh + Ah*Wl + Al*Wh
#define BM 128
#define BN 128
#define BK 32
#define PADE 40
#define ARR_BYTES (128*PADE*2)
#define STAGE_BYTES (4*ARR_BYTES)
#define GSMEM (2*STAGE_BYTES)         // 81920

__device__ __forceinline__ uint32_t smem_u32(const void* p) {
    uint32_t a;
    asm("{ .reg .u64 t; cvta.to.shared.u64 t, %1; cvt.u32.u64 %0, t; }"
        : "=r"(a) : "l"(p));
    return a;
}
__device__ __forceinline__ void cp16(uint32_t dst, const void* src) {
    asm volatile("cp.async.cg.shared.global [%0], [%1], 16;"
                 :: "r"(dst), "l"(src) : "memory");
}
#define CP_COMMIT() asm volatile("cp.async.commit_group;" ::: "memory")
#define CP_WAIT1()  asm volatile("cp.async.wait_group 1;" ::: "memory")
#define CP_WAIT0()  asm volatile("cp.async.wait_group 0;" ::: "memory")

#define LDSM4(r, addr) \
    asm volatile("ldmatrix.sync.aligned.m8n8.x4.shared.b16 {%0,%1,%2,%3}, [%4];" \
        : "=r"((r)[0]), "=r"((r)[1]), "=r"((r)[2]), "=r"((r)[3]) : "r"(addr))
#define LDSM2(r, addr) \
    asm volatile("ldmatrix.sync.aligned.m8n8.x2.shared.b16 {%0,%1}, [%2];" \
        : "=r"((r)[0]), "=r"((r)[1]) : "r"(addr))
#define MMA_BF16(d, a, b) \
    asm volatile("mma.sync.aligned.m16n8k16.row.col.f32.bf16.bf16.f32 " \
        "{%0,%1,%2,%3}, {%4,%5,%6,%7}, {%8,%9}, {%0,%1,%2,%3};" \
        : "+f"((d)[0]), "+f"((d)[1]), "+f"((d)[2]), "+f"((d)[3]) \
        : "r"((a)[0]), "r"((a)[1]), "r"((a)[2]), "r"((a)[3]), \
          "r"((b)[0]), "r"((b)[1]))

__device__ __forceinline__ void load_stage(
        uint32_t sbase,
        const __nv_bfloat16* __restrict__ Ah, const __nv_bfloat16* __restrict__ Al,
        const __nv_bfloat16* __restrict__ Wh, const __nv_bfloat16* __restrict__ Wl,
        int m0, int n0, int k0, int M, int K, int tid) {
    #pragma unroll
    for (int i = 0; i < 8; i++) {
        int idx = tid + i*256;
        int arr = idx >> 9;
        int rem = idx & 511;
        int row = rem >> 2;
        int seg = rem & 3;
        uint32_t dst = sbase + arr*ARR_BYTES + row*(PADE*2) + seg*16;
        const __nv_bfloat16* src;
        if (arr == 0)      { int r = m0 + row; if (r >= M) r = M - 1;
                             src = Ah + (size_t)r*K + k0 + seg*8; }
        else if (arr == 1) { int r = m0 + row; if (r >= M) r = M - 1;
                             src = Al + (size_t)r*K + k0 + seg*8; }
        else if (arr == 2) { src = Wh + (size_t)(n0 + row)*K + k0 + seg*8; }
        else               { src = Wl + (size_t)(n0 + row)*K + k0 + seg*8; }
        cp16(dst, src);
    }
}

__global__ __launch_bounds__(256)
void gemm_mma(const __nv_bfloat16* __restrict__ Ah,
              const __nv_bfloat16* __restrict__ Al,
              const __nv_bfloat16* __restrict__ Wh,
              const __nv_bfloat16* __restrict__ Wl,
              float* __restrict__ C, int M, int N, int K) {
    extern __shared__ char smem[];
    const uint32_t sb = smem_u32(smem);
    const int tid = threadIdx.x;
    const int lane = tid & 31, wid = tid >> 5;
    const int wm = (wid & 1) * 64;
    const int wn = (wid >> 1) * 32;
    const int m0 = blockIdx.y * BM, n0 = blockIdx.x * BN;

    float acc[4][4][4] = {};

    const int ntiles = K / BK;
    load_stage(sb, Ah, Al, Wh, Wl, m0, n0, 0, M, K, tid);
    CP_COMMIT();

    const int arow = lane & 15, acolsel = (lane >> 4) * 8;
    const int brow = lane & 7,  bcolsel = ((lane >> 3) & 1) * 8;

    for (int t = 0; t < ntiles; t++) {
        uint32_t sbase = sb + (t & 1) * STAGE_BYTES;
        if (t + 1 < ntiles) {
            load_stage(sb + ((t + 1) & 1) * STAGE_BYTES,
                       Ah, Al, Wh, Wl, m0, n0, (t + 1) * BK, M, K, tid);
            CP_COMMIT();
            CP_WAIT1();
        } else {
            CP_WAIT0();
        }
        __syncthreads();

        const uint32_t sA_h = sbase;
        const uint32_t sA_l = sbase + ARR_BYTES;
        const uint32_t sW_h = sbase + 2*ARR_BYTES;
        const uint32_t sW_l = sbase + 3*ARR_BYTES;

        #pragma unroll
        for (int ks = 0; ks < 2; ks++) {
            const int kb = ks * 16;
            uint32_t ah[4][4], al[4][4], bh[4][2], bl[4][2];
            #pragma unroll
            for (int mt = 0; mt < 4; mt++) {
                uint32_t off = (wm + mt*16 + arow)*(PADE*2) + (kb + acolsel)*2;
                LDSM4(ah[mt], sA_h + off);
                LDSM4(al[mt], sA_l + off);
            }
            #pragma unroll
            for (int nt = 0; nt < 4; nt++) {
                uint32_t off = (wn + nt*8 + brow)*(PADE*2) + (kb + bcolsel)*2;
                LDSM2(bh[nt], sW_h + off);
                LDSM2(bl[nt], sW_l + off);
            }
            #pragma unroll
            for (int mt = 0; mt < 4; mt++)
                #pragma unroll
                for (int nt = 0; nt < 4; nt++) {
                    MMA_BF16(acc[mt][nt], ah[mt], bh[nt]);
                    MMA_BF16(acc[mt][nt], ah[mt], bl[nt]);
                    MMA_BF16(acc[mt][nt], al[mt], bh[nt]);
                }
        }
        __syncthreads();
    }

    #pragma unroll
    for (int mt = 0; mt < 4; mt++) {
        int rbase = m0 + wm + mt*16 + (lane >> 2);
        #pragma unroll
        for (int half = 0; half < 2; half++) {
            int r = rbase + half*8;
            if (r < M) {
                float* crow = C + (size_t)r*N + n0 + wn + (lane & 3)*2;
                #pragma unroll
                for (int nt = 0; nt < 4; nt++) {
                    float2 v = make_float2(acc[mt][nt][half*2],
                                           acc[mt][nt][half*2 + 1]);
                    *reinterpret_cast<float2*>(crow + nt*8) = v;
                }
            }
        }
    }
}

// ---------------- fp32 -> bf16 hi/lo split, strided repack -----------------
__global__ void cvt_pack(const float* __restrict__ src,
                         __nv_bfloat16* __restrict__ hi,
                         __nv_bfloat16* __restrict__ lo,
                         int chunk, long long dst_stride, int n) {
    int i = blockIdx.x * blockDim.x + threadIdx.x;
    if (i >= n) return;
    int l2 = i / chunk, j = i - l2*chunk;
    size_t di = (size_t)l2*dst_stride + j;
    float x = src[i];
    __nv_bfloat16 h = __float2bfloat16(x);
    hi[di] = h;
    lo[di] = __float2bfloat16(x - __bfloat162float(h));
}

// ---------------- patch embed (writes fp32 h + bf16 hi/lo) -----------------
__global__ void patch_embed(const float* __restrict__ x,
                            const float* __restrict__ pw,
                            const float* __restrict__ pb,
                            const float* __restrict__ pos,
                            float* __restrict__ h,
                            __nv_bfloat16* __restrict__ ah,
                            __nv_bfloat16* __restrict__ al) {
    int bp = blockIdx.x;
    int b = bp / NP_, pidx = bp % NP_;
    int gi = pidx / 14, gj = pidx % 14;
    __shared__ float patch[768];
    for (int i = threadIdx.x; i < 768; i += blockDim.x) {
        int c  = i >> 8;
        int r  = i & 255;
        int ii = r >> 4, jj = r & 15;
        patch[i] = x[((b*3 + c)*224 + gi*16 + ii)*224 + gj*16 + jj];
    }
    __syncthreads();
    for (int e = threadIdx.x; e < E_; e += blockDim.x) {
        const float* w = pw + e*768;
        float acc = 0.f;
        #pragma unroll 8
        for (int i = 0; i < 768; i++) acc = fmaf(patch[i], w[i], acc);
        float val = acc + pb[e] + pos[(1 + pidx)*E_ + e];
        size_t oi = (size_t)(b*N_ + 1 + pidx)*E_ + e;
        h[oi] = val;
        __nv_bfloat16 hh = __float2bfloat16(val);
        ah[oi] = hh;
        al[oi] = __float2bfloat16(val - __bfloat162float(hh));
    }
}

__global__ void cls_pos(const float* __restrict__ cls,
                        const float* __restrict__ pos,
                        float* __restrict__ h,
                        __nv_bfloat16* __restrict__ ah,
                        __nv_bfloat16* __restrict__ al) {
    int b = blockIdx.x;
    for (int e = threadIdx.x; e < E_; e += blockDim.x) {
        float val = cls[e] + pos[e];
        size_t oi = (size_t)(b*N_)*E_ + e;
        h[oi] = val;
        __nv_bfloat16 hh = __float2bfloat16(val);
        ah[oi] = hh;
        al[oi] = __float2bfloat16(val - __bfloat162float(hh));
    }
}

// ---------------- fused attention: one block per (b,h) ----------------------
// qkv[ROWS][2304]: q cols 0..767, k 768..1535, v 1536..2303 (per head h: +h*64)
// Fuses: q/k cosine-norm + scale, softmax (fixed bias, no max pass), AV,
// bf16 hi/lo output split.
#define AT_PAD 65
#define ASMEM_FLOATS (2*197*AT_PAD + 197 + 64 + 64 + 4*64 + 8 + 4)
#define ASMEM_BYTES  (ASMEM_FLOATS*4)

__global__ __launch_bounds__(256)
void attn_fused(const float* __restrict__ qkv,
                const float* __restrict__ s_qk,
                __nv_bfloat16* __restrict__ ah,
                __nv_bfloat16* __restrict__ al) {
    extern __shared__ float sm[];
    float* Ks = sm;                          // 197*65
    float* Vs = Ks + 197*AT_PAD;             // 197*65
    float* lg = Vs + 197*AT_PAD;             // 197
    float* qs = lg + 197;                    // 64
    float* ss = qs + 64;                     // 64
    float* acc4 = ss + 64;                   // 4*64
    float* red = acc4 + 256;                 // 8
    float* invp = red + 8;                   // 1

    int bh = blockIdx.x;
    int h = bh % H_, b = bh / H_;
    int tid = threadIdx.x, wid = tid >> 5, lane = tid & 31;
    const float* qb = qkv + (size_t)(b*N_)*(3*E_) + h*HD_;

    if (tid < 64) ss[tid] = s_qk[h*HD_ + tid] * SQRTE;
    for (int i = tid; i < 197*64; i += 256) {
        int m = i >> 6, d = i & 63;
        Ks[m*AT_PAD + d] = qb[(size_t)m*(3*E_) + E_ + d];
        Vs[m*AT_PAD + d] = qb[(size_t)m*(3*E_) + 2*E_ + d];
    }
    __syncthreads();
    // normalize K rows in smem (cosine-norm * s)
    for (int m = wid; m < N_; m += 8) {
        float v0 = Ks[m*AT_PAD + lane], v1 = Ks[m*AT_PAD + 32 + lane];
        float sq = v0*v0 + v1*v1;
        #pragma unroll
        for (int o = 16; o > 0; o >>= 1) sq += __shfl_xor_sync(~0u, sq, o);
        float inv = 1.f / fmaxf(sqrtf(sq), 1e-6f);
        Ks[m*AT_PAD + lane]      = v0 * inv * ss[lane];
        Ks[m*AT_PAD + 32 + lane] = v1 * inv * ss[lane + 32];
    }
    __syncthreads();

    for (int qn = 0; qn < N_; qn++) {
        if (wid == 0) {
            float v0 = qb[(size_t)qn*(3*E_) + lane];
            float v1 = qb[(size_t)qn*(3*E_) + 32 + lane];
            float sq = v0*v0 + v1*v1;
            #pragma unroll
            for (int o = 16; o > 0; o >>= 1) sq += __shfl_xor_sync(~0u, sq, o);
            float inv = 1.f / fmaxf(sqrtf(sq), 1e-6f);
            qs[lane]      = v0 * inv * ss[lane];
            qs[lane + 32] = v1 * inv * ss[lane + 32];
        }
        __syncthreads();
        // scores + exp (logits bounded: |q.k| <= ~1, *8 -> [-8,8]; fixed bias)
        float p = 0.f;
        if (tid < N_) {
            const float* kr = Ks + tid*AT_PAD;
            float sacc = 0.f;
            #pragma unroll
            for (int d = 0; d < 64; d++) sacc = fmaf(qs[d], kr[d], sacc);
            p = expf(sacc * 8.0f - 8.0f);
            lg[tid] = p;
        }
        float ws = p;
        #pragma unroll
        for (int o = 16; o > 0; o >>= 1) ws += __shfl_xor_sync(~0u, ws, o);
        if (lane == 0) red[wid] = ws;
        __syncthreads();
        if (tid == 0) {
            float s = 0.f;
            #pragma unroll
            for (int i = 0; i < 8; i++) s += red[i];
            invp[0] = 1.f / s;
        }
        // AV
        int d = tid & 63, c = tid >> 6;
        float acc = 0.f;
        for (int m = c; m < N_; m += 4)
            acc = fmaf(lg[m], Vs[m*AT_PAD + d], acc);
        acc4[c*64 + d] = acc;
        __syncthreads();
        if (tid < 64) {
            float o2 = (acc4[tid] + acc4[64 + tid] + acc4[128 + tid] +
                        acc4[192 + tid]) * invp[0];
            size_t oi = ((size_t)(b*N_) + qn)*E_ + h*HD_ + tid;
            __nv_bfloat16 hh = __float2bfloat16(o2);
            ah[oi] = hh;
            al[oi] = __float2bfloat16(o2 - __bfloat162float(hh));
        }
        __syncthreads();
    }
}

// ---------------- residual + double cosine-norm (+ bf16 split out) ----------
__global__ __launch_bounds__(256)
void res_cn(float* __restrict__ h, const float* __restrict__ d,
            const float* __restrict__ alpha,
            __nv_bfloat16* __restrict__ ah, __nv_bfloat16* __restrict__ al) {
    int row = blockIdx.x;
    int tid = threadIdx.x;
    const float* dr = d + (size_t)row*E_;
    float* hr = h + (size_t)row*E_;
    __shared__ float red[256];
    float dv[3], hv[3];
    float ss = 0.f;
    #pragma unroll
    for (int t = 0; t < 3; t++) {
        int e = tid + t*256;
        dv[t] = dr[e]; hv[t] = hr[e];
        ss += dv[t]*dv[t];
    }
    red[tid] = ss; __syncthreads();
    for (int s = 128; s > 0; s >>= 1) {
        if (tid < s) red[tid] += red[tid + s];
        __syncthreads();
    }
    float inv1 = 1.0f / fmaxf(sqrtf(red[0]), 1e-6f);
    __syncthreads();
    float y[3]; float ss2 = 0.f;
    #pragma unroll
    for (int t = 0; t < 3; t++) {
        int e = tid + t*256;
        float a = alpha[e] * (0.05f * SQRTE);
        y[t] = hv[t] + a*(dv[t]*inv1 - hv[t]);
        ss2 += y[t]*y[t];
    }
    red[tid] = ss2; __syncthreads();
    for (int s = 128; s > 0; s >>= 1) {
        if (tid < s) red[tid] += red[tid + s];
        __syncthreads();
    }
    float inv2 = 1.0f / fmaxf(sqrtf(red[0]), 1e-6f);
    #pragma unroll
    for (int t = 0; t < 3; t++) {
        int e = tid + t*256;
        float val = y[t]*inv2;
        hr[e] = val;
        __nv_bfloat16 hh = __float2bfloat16(val);
        size_t oi = (size_t)row*E_ + e;
        ah[oi] = hh;
        al[oi] = __float2bfloat16(val - __bfloat162float(hh));
    }
}

// ---------------- MLP activation (packed ug -> bf16 hi/lo) ------------------
__global__ void mlp_act(const float* __restrict__ ug,
                        const float* __restrict__ s_u, const float* __restrict__ s_v,
                        __nv_bfloat16* __restrict__ ah, __nv_bfloat16* __restrict__ al) {
    int i = blockIdx.x*blockDim.x + threadIdx.x;
    if (i >= ROWS_*FF_) return;
    int row = i / FF_, j = i - row*FF_;
    float uu = ug[(size_t)row*(2*FF_) + j] * s_u[j];
    float vv = ug[(size_t)row*(2*FF_) + FF_ + j] * s_v[j] * SQRTE;
    float sig = 1.0f/(1.0f + expf(-vv));
    float val = uu*vv*sig;
    __nv_bfloat16 hh = __float2bfloat16(val);
    ah[i] = hh;
    al[i] = __float2bfloat16(val - __bfloat162float(hh));
}

// ---------------- LayerNorm tap -> output (drop CLS token) ------------------
__global__ __launch_bounds__(256)
void ln_out(const float* __restrict__ h, const float* __restrict__ w,
            const float* __restrict__ b, float* __restrict__ o) {
    int br = blockIdx.x;
    int bb = br / NP_, n = br % NP_ + 1;
    const float* hr = h + (size_t)(bb*N_ + n)*E_;
    float* orow = o + (size_t)br*E_;
    __shared__ float red[256];
    int tid = threadIdx.x;
    float vv[3];
    float s = 0.f;
    #pragma unroll
    for (int t = 0; t < 3; t++) { vv[t] = hr[tid + t*256]; s += vv[t]; }
    red[tid] = s; __syncthreads();
    for (int st = 128; st > 0; st >>= 1) {
        if (tid < st) red[tid] += red[tid + st];
        __syncthreads();
    }
    float mean = red[0] * (1.0f/E_);
    __syncthreads();
    float s2 = 0.f;
    #pragma unroll
    for (int t = 0; t < 3; t++) { float dd = vv[t] - mean; s2 += dd*dd; }
    red[tid] = s2; __syncthreads();
    for (int st = 128; st > 0; st >>= 1) {
        if (tid < st) red[tid] += red[tid + st];
        __syncthreads();
    }
    float inv = rsqrtf(red[0]*(1.0f/E_) + 1e-6f);
    #pragma unroll
    for (int t = 0; t < 3; t++) {
        int e = tid + t*256;
        orow[e] = (vv[t] - mean)*inv*w[e] + b[e];
    }
}

// ======================= driver ==============================================
extern "C" void kernel_launch(void* const* d_in, const int* in_sizes, int n_in,
                              void* d_out, int out_size) {
    (void)in_sizes; (void)n_in; (void)out_size;
    const float* x       = (const float*)d_in[0];
    const float* patch_w = (const float*)d_in[1];
    const float* patch_b = (const float*)d_in[2];
    const float* cls     = (const float*)d_in[3];
    const float* pos     = (const float*)d_in[4];
    const float* Wq      = (const float*)d_in[5];
    const float* Wk      = (const float*)d_in[6];
    const float* Wv      = (const float*)d_in[7];
    const float* Wo      = (const float*)d_in[8];
    const float* s_qk    = (const float*)d_in[9];
    const float* Wup     = (const float*)d_in[10];
    const float* Wgate   = (const float*)d_in[11];
    const float* Wdown   = (const float*)d_in[12];
    const float* s_u     = (const float*)d_in[13];
    const float* s_v     = (const float*)d_in[14];
    const float* aA      = (const float*)d_in[15];
    const float* aM      = (const float*)d_in[16];
    const float* fcw     = (const float*)d_in[17];
    const float* fcb     = (const float*)d_in[18];
    float* out = (float*)d_out;

    float *h, *t, *qkv, *ug;
    __nv_bfloat16 *ah, *al, *wh, *wl;
    cudaGetSymbolAddress((void**)&h,   g_h);
    cudaGetSymbolAddress((void**)&t,   g_t);
    cudaGetSymbolAddress((void**)&qkv, g_qkv);
    cudaGetSymbolAddress((void**)&ug,  g_ug);
    cudaGetSymbolAddress((void**)&ah,  g_act_hi);
    cudaGetSymbolAddress((void**)&al,  g_act_lo);
    cudaGetSymbolAddress((void**)&wh,  g_w_hi);
    cudaGetSymbolAddress((void**)&wl,  g_w_lo);

    cudaFuncSetAttribute(gemm_mma, cudaFuncAttributeMaxDynamicSharedMemorySize, GSMEM);
    cudaFuncSetAttribute(attn_fused, cudaFuncAttributeMaxDynamicSharedMemorySize, ASMEM_BYTES);

    // weight split + repack (every call; deterministic)
    cvt_pack<<<(NQ_ +255)/256, 256>>>(Wq, wh+OFF_QKV,        wl+OFF_QKV,        EE_,  3LL*EE_,  NQ_);
    cvt_pack<<<(NQ_ +255)/256, 256>>>(Wk, wh+OFF_QKV+EE_,    wl+OFF_QKV+EE_,    EE_,  3LL*EE_,  NQ_);
    cvt_pack<<<(NQ_ +255)/256, 256>>>(Wv, wh+OFF_QKV+2*EE_,  wl+OFF_QKV+2*EE_,  EE_,  3LL*EE_,  NQ_);
    cvt_pack<<<(NQ_ +255)/256, 256>>>(Wo, wh+OFF_O,          wl+OFF_O,          EE_,  (long long)EE_, NQ_);
    cvt_pack<<<(NUP_+255)/256, 256>>>(Wup,   wh+OFF_UG,      wl+OFF_UG,         FFE_, 2LL*FFE_, NUP_);
    cvt_pack<<<(NUP_+255)/256, 256>>>(Wgate, wh+OFF_UG+FFE_, wl+OFF_UG+FFE_,    FFE_, 2LL*FFE_, NUP_);
    cvt_pack<<<(NUP_+255)/256, 256>>>(Wdown, wh+OFF_DOWN,    wl+OFF_DOWN,       FFE_, (long long)FFE_, NUP_);

    patch_embed<<<B_*NP_, 256>>>(x, patch_w, patch_b, pos, h, ah, al);
    cls_pos<<<B_, 256>>>(cls, pos, h, ah, al);

    dim3 gQKV(3*E_/BN, (ROWS_ + BM - 1)/BM);  // (18, 25)
    dim3 gE(E_/BN, (ROWS_ + BM - 1)/BM);      // (6, 25)
    dim3 gUG(2*FF_/BN, (ROWS_ + BM - 1)/BM);  // (48, 25)
    const int nF = ROWS_*FF_;

    for (int l = 0; l < L_; l++) {
        const size_t oqkv = (size_t)l*3*EE_;
        const size_t oo   = (size_t)l*EE_;
        const size_t oug  = (size_t)l*2*FFE_;
        const size_t od   = (size_t)l*FFE_;
        gemm_mma<<<gQKV, 256, GSMEM>>>(ah, al, wh+OFF_QKV+oqkv, wl+OFF_QKV+oqkv,
                                       qkv, ROWS_, 3*E_, E_);
        attn_fused<<<B_*H_, 256, ASMEM_BYTES>>>(qkv, s_qk + (size_t)l*H_*HD_, ah, al);
        gemm_mma<<<gE, 256, GSMEM>>>(ah, al, wh+OFF_O+oo, wl+OFF_O+oo,
                                     t, ROWS_, E_, E_);
        res_cn<<<ROWS_, 256>>>(h, t, aA + (size_t)l*E_, ah, al);
        gemm_mma<<<gUG, 256, GSMEM>>>(ah, al, wh+OFF_UG+oug, wl+OFF_UG+oug,
                                      ug, ROWS_, 2*FF_, E_);
        mlp_act<<<(nF + 255)/256, 256>>>(ug, s_u + (size_t)l*FF_, s_v + (size_t)l*FF_, ah, al);
        gemm_mma<<<gE, 256, GSMEM>>>(ah, al, wh+OFF_DOWN+od, wl+OFF_DOWN+od,
                                     t, ROWS_, E_, FF_);
        res_cn<<<ROWS_, 256>>>(h, t, aM + (size_t)l*E_, ah, al);
        if (l == L_ - 2)
            ln_out<<<B_*NP_, 256>>>(h, fcw, fcb, out);
    }
    ln_out<<<B_*NP_, 256>>>(h, fcw, fcb, out + (size_t)B_*NP_*E_);
}

// round 5
// speedup vs baseline: 3.0601x; 1.0018x over previous
#include <cuda_runtime.h>
#include <cuda_bf16.h>
#include <math.h>
#include <stdint.h>

#define B_   16
#define E_   768
#define H_   12
#define HD_  64
#define N_   197
#define NP_  196
#define L_   12
#define FF_  3072
#define ROWS_ (B_*N_)          // 3152
#define SQRTE 27.712812921102035f
#define EE_   (E_*E_)
#define FFE_  (FF_*E_)

// packed bf16 weight layout: [QKV(3*NQ)] [O(NQ)] [UPGATE(2*NUP)] [DOWN(NUP)]
#define NQ_   (L_*EE_)
#define NUP_  (L_*FFE_)
#define OFF_QKV  0
#define OFF_O    (3*NQ_)
#define OFF_UG   (4*NQ_)
#define OFF_DOWN (4*NQ_ + 2*NUP_)
#define WTOT_    (4*NQ_ + 3*NUP_)

// ---------------- scratch (device globals; no allocation allowed) ----------
__device__ float g_h[ROWS_*E_];
__device__ float g_t[ROWS_*E_];
__device__ float g_qkv[ROWS_*3*E_];
__device__ float g_ug[ROWS_*2*FF_];
__device__ __nv_bfloat16 g_act_hi[ROWS_*FF_];
__device__ __nv_bfloat16 g_act_lo[ROWS_*FF_];
__device__ __nv_bfloat16 g_w_hi[WTOT_];
__device__ __nv_bfloat16 g_w_lo[WTOT_];

// ======================= mma.sync GEMM ======================================
// C[M,N] = A[M,K] * W[N,K]^T ; A,W bf16 hi/lo pairs, fp32 accum.
// D = Ah*Wh + Ah*Wl + Al*Wh.  4 warps, warp tile 64x64, CTA tile 128x128.
#define BM 128
#define BN 128
#define BK 32
#define PADE 40
#define ARR_BYTES (128*PADE*2)
#define STAGE_BYTES (4*ARR_BYTES)
#define GSMEM (2*STAGE_BYTES)         // 81920

__device__ __forceinline__ uint32_t smem_u32(const void* p) {
    uint32_t a;
    asm("{ .reg .u64 t; cvta.to.shared.u64 t, %1; cvt.u32.u64 %0, t; }"
        : "=r"(a) : "l"(p));
    return a;
}
__device__ __forceinline__ void cp16(uint32_t dst, const void* src) {
    asm volatile("cp.async.cg.shared.global [%0], [%1], 16;"
                 :: "r"(dst), "l"(src) : "memory");
}
#define CP_COMMIT() asm volatile("cp.async.commit_group;" ::: "memory")
#define CP_WAIT1()  asm volatile("cp.async.wait_group 1;" ::: "memory")
#define CP_WAIT0()  asm volatile("cp.async.wait_group 0;" ::: "memory")

#define LDSM4(r, addr) \
    asm volatile("ldmatrix.sync.aligned.m8n8.x4.shared.b16 {%0,%1,%2,%3}, [%4];" \
        : "=r"((r)[0]), "=r"((r)[1]), "=r"((r)[2]), "=r"((r)[3]) : "r"(addr))
#define MMA_BF16(d, a, b0, b1) \
    asm volatile("mma.sync.aligned.m16n8k16.row.col.f32.bf16.bf16.f32 " \
        "{%0,%1,%2,%3}, {%4,%5,%6,%7}, {%8,%9}, {%0,%1,%2,%3};" \
        : "+f"((d)[0]), "+f"((d)[1]), "+f"((d)[2]), "+f"((d)[3]) \
        : "r"((a)[0]), "r"((a)[1]), "r"((a)[2]), "r"((a)[3]), \
          "r"(b0), "r"(b1))

__device__ __forceinline__ void load_stage(
        uint32_t sbase,
        const __nv_bfloat16* __restrict__ Ah, const __nv_bfloat16* __restrict__ Al,
        const __nv_bfloat16* __restrict__ Wh, const __nv_bfloat16* __restrict__ Wl,
        int m0, int n0, int k0, int M, int K, int tid) {
    #pragma unroll
    for (int i = 0; i < 16; i++) {
        int idx = tid + i*128;
        int arr = idx >> 9;
        int rem = idx & 511;
        int row = rem >> 2;
        int seg = rem & 3;
        uint32_t dst = sbase + arr*ARR_BYTES + row*(PADE*2) + seg*16;
        const __nv_bfloat16* src;
        if (arr == 0)      { int r = m0 + row; if (r >= M) r = M - 1;
                             src = Ah + (size_t)r*K + k0 + seg*8; }
        else if (arr == 1) { int r = m0 + row; if (r >= M) r = M - 1;
                             src = Al + (size_t)r*K + k0 + seg*8; }
        else if (arr == 2) { src = Wh + (size_t)(n0 + row)*K + k0 + seg*8; }
        else               { src = Wl + (size_t)(n0 + row)*K + k0 + seg*8; }
        cp16(dst, src);
    }
}

__global__ __launch_bounds__(128)
void gemm_mma(const __nv_bfloat16* __restrict__ Ah,
              const __nv_bfloat16* __restrict__ Al,
              const __nv_bfloat16* __restrict__ Wh,
              const __nv_bfloat16* __restrict__ Wl,
              float* __restrict__ C, int M, int N, int K) {
    extern __shared__ char smem[];
    const uint32_t sb = smem_u32(smem);
    const int tid = threadIdx.x;
    const int lane = tid & 31, wid = tid >> 5;      // 4 warps
    const int wm = (wid & 1) * 64;
    const int wn = (wid >> 1) * 64;
    const int m0 = blockIdx.y * BM, n0 = blockIdx.x * BN;

    float acc[4][8][4] = {};

    const int ntiles = K / BK;
    load_stage(sb, Ah, Al, Wh, Wl, m0, n0, 0, M, K, tid);
    CP_COMMIT();

    const int arow = lane & 15, acolsel = (lane >> 4) * 8;

    for (int t = 0; t < ntiles; t++) {
        uint32_t sbase = sb + (t & 1) * STAGE_BYTES;
        if (t + 1 < ntiles) {
            load_stage(sb + ((t + 1) & 1) * STAGE_BYTES,
                       Ah, Al, Wh, Wl, m0, n0, (t + 1) * BK, M, K, tid);
            CP_COMMIT();
            CP_WAIT1();
        } else {
            CP_WAIT0();
        }
        __syncthreads();

        const uint32_t sA_h = sbase;
        const uint32_t sA_l = sbase + ARR_BYTES;
        const uint32_t sW_h = sbase + 2*ARR_BYTES;
        const uint32_t sW_l = sbase + 3*ARR_BYTES;

        #pragma unroll
        for (int ks = 0; ks < 2; ks++) {
            const int kb = ks * 16;
            uint32_t ah[4][4], al[4][4], bh[4][4], bl[4][4];
            #pragma unroll
            for (int mt = 0; mt < 4; mt++) {
                uint32_t off = (wm + mt*16 + arow)*(PADE*2) + (kb + acolsel)*2;
                LDSM4(ah[mt], sA_h + off);
                LDSM4(al[mt], sA_l + off);
            }
            #pragma unroll
            for (int nb = 0; nb < 4; nb++) {
                uint32_t off = (wn + nb*16 + arow)*(PADE*2) + (kb + acolsel)*2;
                LDSM4(bh[nb], sW_h + off);
                LDSM4(bl[nb], sW_l + off);
            }
            #pragma unroll
            for (int mt = 0; mt < 4; mt++)
                #pragma unroll
                for (int nb = 0; nb < 4; nb++) {
                    // nt = 2*nb   : fragment {r0, r2}
                    MMA_BF16(acc[mt][2*nb],   ah[mt], bh[nb][0], bh[nb][2]);
                    MMA_BF16(acc[mt][2*nb],   ah[mt], bl[nb][0], bl[nb][2]);
                    MMA_BF16(acc[mt][2*nb],   al[mt], bh[nb][0], bh[nb][2]);
                    // nt = 2*nb+1 : fragment {r1, r3}
                    MMA_BF16(acc[mt][2*nb+1], ah[mt], bh[nb][1], bh[nb][3]);
                    MMA_BF16(acc[mt][2*nb+1], ah[mt], bl[nb][1], bl[nb][3]);
                    MMA_BF16(acc[mt][2*nb+1], al[mt], bh[nb][1], bh[nb][3]);
                }
        }
        __syncthreads();
    }

    #pragma unroll
    for (int mt = 0; mt < 4; mt++) {
        int rbase = m0 + wm + mt*16 + (lane >> 2);
        #pragma unroll
        for (int half = 0; half < 2; half++) {
            int r = rbase + half*8;
            if (r < M) {
                float* crow = C + (size_t)r*N + n0 + wn + (lane & 3)*2;
                #pragma unroll
                for (int nt = 0; nt < 8; nt++) {
                    float2 v = make_float2(acc[mt][nt][half*2],
                                           acc[mt][nt][half*2 + 1]);
                    *reinterpret_cast<float2*>(crow + nt*8) = v;
                }
            }
        }
    }
}

// ---------------- fp32 -> bf16 hi/lo split, strided repack (x4 vector) ------
__global__ void cvt_pack4(const float4* __restrict__ src,
                          __nv_bfloat162* __restrict__ hi,
                          __nv_bfloat162* __restrict__ lo,
                          int chunk4, long long dst_stride2, int n4) {
    int i = blockIdx.x * blockDim.x + threadIdx.x;
    if (i >= n4) return;
    int l2 = i / chunk4, j = i - l2*chunk4;
    size_t di = (size_t)l2*dst_stride2 + (size_t)j*2;
    float4 x = src[i];
    __nv_bfloat16 h0 = __float2bfloat16(x.x), h1 = __float2bfloat16(x.y);
    __nv_bfloat16 h2 = __float2bfloat16(x.z), h3 = __float2bfloat16(x.w);
    hi[di]   = __nv_bfloat162(h0, h1);
    hi[di+1] = __nv_bfloat162(h2, h3);
    lo[di]   = __nv_bfloat162(__float2bfloat16(x.x - __bfloat162float(h0)),
                              __float2bfloat16(x.y - __bfloat162float(h1)));
    lo[di+1] = __nv_bfloat162(__float2bfloat16(x.z - __bfloat162float(h2)),
                              __float2bfloat16(x.w - __bfloat162float(h3)));
}

// ---------------- patch embed (writes fp32 h + bf16 hi/lo) -----------------
__global__ void patch_embed(const float* __restrict__ x,
                            const float* __restrict__ pw,
                            const float* __restrict__ pb,
                            const float* __restrict__ pos,
                            float* __restrict__ h,
                            __nv_bfloat16* __restrict__ ah,
                            __nv_bfloat16* __restrict__ al) {
    int bp = blockIdx.x;
    int b = bp / NP_, pidx = bp % NP_;
    int gi = pidx / 14, gj = pidx % 14;
    __shared__ float patch[768];
    for (int i = threadIdx.x; i < 768; i += blockDim.x) {
        int c  = i >> 8;
        int r  = i & 255;
        int ii = r >> 4, jj = r & 15;
        patch[i] = x[((b*3 + c)*224 + gi*16 + ii)*224 + gj*16 + jj];
    }
    __syncthreads();
    for (int e = threadIdx.x; e < E_; e += blockDim.x) {
        const float* w = pw + e*768;
        float acc = 0.f;
        #pragma unroll 8
        for (int i = 0; i < 768; i++) acc = fmaf(patch[i], w[i], acc);
        float val = acc + pb[e] + pos[(1 + pidx)*E_ + e];
        size_t oi = (size_t)(b*N_ + 1 + pidx)*E_ + e;
        h[oi] = val;
        __nv_bfloat16 hh = __float2bfloat16(val);
        ah[oi] = hh;
        al[oi] = __float2bfloat16(val - __bfloat162float(hh));
    }
}

__global__ void cls_pos(const float* __restrict__ cls,
                        const float* __restrict__ pos,
                        float* __restrict__ h,
                        __nv_bfloat16* __restrict__ ah,
                        __nv_bfloat16* __restrict__ al) {
    int b = blockIdx.x;
    for (int e = threadIdx.x; e < E_; e += blockDim.x) {
        float val = cls[e] + pos[e];
        size_t oi = (size_t)(b*N_)*E_ + e;
        h[oi] = val;
        __nv_bfloat16 hh = __float2bfloat16(val);
        ah[oi] = hh;
        al[oi] = __float2bfloat16(val - __bfloat162float(hh));
    }
}

// ---------------- fused attention: one block per (b,h) ----------------------
#define AT_PAD 65
#define ASMEM_FLOATS (2*197*AT_PAD + 197 + 64 + 64 + 4*64 + 8 + 4)
#define ASMEM_BYTES  (ASMEM_FLOATS*4)

__global__ __launch_bounds__(256)
void attn_fused(const float* __restrict__ qkv,
                const float* __restrict__ s_qk,
                __nv_bfloat16* __restrict__ ah,
                __nv_bfloat16* __restrict__ al) {
    extern __shared__ float sm[];
    float* Ks = sm;
    float* Vs = Ks + 197*AT_PAD;
    float* lg = Vs + 197*AT_PAD;
    float* qs = lg + 197;
    float* ss = qs + 64;
    float* acc4 = ss + 64;
    float* red = acc4 + 256;
    float* invp = red + 8;

    int bh = blockIdx.x;
    int h = bh % H_, b = bh / H_;
    int tid = threadIdx.x, wid = tid >> 5, lane = tid & 31;
    const float* qb = qkv + (size_t)(b*N_)*(3*E_) + h*HD_;

    if (tid < 64) ss[tid] = s_qk[h*HD_ + tid] * SQRTE;
    for (int i = tid; i < 197*64; i += 256) {
        int m = i >> 6, d = i & 63;
        Ks[m*AT_PAD + d] = qb[(size_t)m*(3*E_) + E_ + d];
        Vs[m*AT_PAD + d] = qb[(size_t)m*(3*E_) + 2*E_ + d];
    }
    __syncthreads();
    for (int m = wid; m < N_; m += 8) {
        float v0 = Ks[m*AT_PAD + lane], v1 = Ks[m*AT_PAD + 32 + lane];
        float sq = v0*v0 + v1*v1;
        #pragma unroll
        for (int o = 16; o > 0; o >>= 1) sq += __shfl_xor_sync(~0u, sq, o);
        float inv = 1.f / fmaxf(sqrtf(sq), 1e-6f);
        Ks[m*AT_PAD + lane]      = v0 * inv * ss[lane];
        Ks[m*AT_PAD + 32 + lane] = v1 * inv * ss[lane + 32];
    }
    __syncthreads();

    for (int qn = 0; qn < N_; qn++) {
        if (wid == 0) {
            float v0 = qb[(size_t)qn*(3*E_) + lane];
            float v1 = qb[(size_t)qn*(3*E_) + 32 + lane];
            float sq = v0*v0 + v1*v1;
            #pragma unroll
            for (int o = 16; o > 0; o >>= 1) sq += __shfl_xor_sync(~0u, sq, o);
            float inv = 1.f / fmaxf(sqrtf(sq), 1e-6f);
            qs[lane]      = v0 * inv * ss[lane];
            qs[lane + 32] = v1 * inv * ss[lane + 32];
        }
        __syncthreads();
        float p = 0.f;
        if (tid < N_) {
            const float* kr = Ks + tid*AT_PAD;
            float sacc = 0.f;
            #pragma unroll
            for (int d = 0; d < 64; d++) sacc = fmaf(qs[d], kr[d], sacc);
            p = expf(sacc * 8.0f - 8.0f);
            lg[tid] = p;
        }
        float ws = p;
        #pragma unroll
        for (int o = 16; o > 0; o >>= 1) ws += __shfl_xor_sync(~0u, ws, o);
        if (lane == 0) red[wid] = ws;
        __syncthreads();
        if (tid == 0) {
            float s = 0.f;
            #pragma unroll
            for (int i = 0; i < 8; i++) s += red[i];
            invp[0] = 1.f / s;
        }
        int d = tid & 63, c = tid >> 6;
        float acc = 0.f;
        for (int m = c; m < N_; m += 4)
            acc = fmaf(lg[m], Vs[m*AT_PAD + d], acc);
        acc4[c*64 + d] = acc;
        __syncthreads();
        if (tid < 64) {
            float o2 = (acc4[tid] + acc4[64 + tid] + acc4[128 + tid] +
                        acc4[192 + tid]) * invp[0];
            size_t oi = ((size_t)(b*N_) + qn)*E_ + h*HD_ + tid;
            __nv_bfloat16 hh = __float2bfloat16(o2);
            ah[oi] = hh;
            al[oi] = __float2bfloat16(o2 - __bfloat162float(hh));
        }
        __syncthreads();
    }
}

// ---------------- residual + double cosine-norm (+ bf16 split out) ----------
__global__ __launch_bounds__(256)
void res_cn(float* __restrict__ h, const float* __restrict__ d,
            const float* __restrict__ alpha,
            __nv_bfloat16* __restrict__ ah, __nv_bfloat16* __restrict__ al) {
    int row = blockIdx.x;
    int tid = threadIdx.x;
    const float* dr = d + (size_t)row*E_;
    float* hr = h + (size_t)row*E_;
    __shared__ float red[256];
    float dv[3], hv[3];
    float ss = 0.f;
    #pragma unroll
    for (int t = 0; t < 3; t++) {
        int e = tid + t*256;
        dv[t] = dr[e]; hv[t] = hr[e];
        ss += dv[t]*dv[t];
    }
    red[tid] = ss; __syncthreads();
    for (int s = 128; s > 0; s >>= 1) {
        if (tid < s) red[tid] += red[tid + s];
        __syncthreads();
    }
    float inv1 = 1.0f / fmaxf(sqrtf(red[0]), 1e-6f);
    __syncthreads();
    float y[3]; float ss2 = 0.f;
    #pragma unroll
    for (int t = 0; t < 3; t++) {
        int e = tid + t*256;
        float a = alpha[e] * (0.05f * SQRTE);
        y[t] = hv[t] + a*(dv[t]*inv1 - hv[t]);
        ss2 += y[t]*y[t];
    }
    red[tid] = ss2; __syncthreads();
    for (int s = 128; s > 0; s >>= 1) {
        if (tid < s) red[tid] += red[tid + s];
        __syncthreads();
    }
    float inv2 = 1.0f / fmaxf(sqrtf(red[0]), 1e-6f);
    #pragma unroll
    for (int t = 0; t < 3; t++) {
        int e = tid + t*256;
        float val = y[t]*inv2;
        hr[e] = val;
        __nv_bfloat16 hh = __float2bfloat16(val);
        size_t oi = (size_t)row*E_ + e;
        ah[oi] = hh;
        al[oi] = __float2bfloat16(val - __bfloat162float(hh));
    }
}

// ---------------- MLP activation (packed ug -> bf16 hi/lo, x4 vector) -------
__global__ void mlp_act(const float4* __restrict__ ug,
                        const float4* __restrict__ s_u, const float4* __restrict__ s_v,
                        __nv_bfloat162* __restrict__ ah, __nv_bfloat162* __restrict__ al) {
    int i = blockIdx.x*blockDim.x + threadIdx.x;      // over ROWS_*FF_/4
    if (i >= ROWS_*FF_/4) return;
    int row = i / (FF_/4), j = i - row*(FF_/4);
    float4 uu = ug[(size_t)row*(2*FF_/4) + j];
    float4 vv = ug[(size_t)row*(2*FF_/4) + FF_/4 + j];
    float4 su = s_u[j], sv = s_v[j];
    float o0, o1, o2, o3;
    {
        float a = uu.x*su.x, b = vv.x*sv.x*SQRTE;
        o0 = a*b/(1.0f + expf(-b));
        a = uu.y*su.y; b = vv.y*sv.y*SQRTE;
        o1 = a*b/(1.0f + expf(-b));
        a = uu.z*su.z; b = vv.z*sv.z*SQRTE;
        o2 = a*b/(1.0f + expf(-b));
        a = uu.w*su.w; b = vv.w*sv.w*SQRTE;
        o3 = a*b/(1.0f + expf(-b));
    }
    __nv_bfloat16 h0 = __float2bfloat16(o0), h1 = __float2bfloat16(o1);
    __nv_bfloat16 h2 = __float2bfloat16(o2), h3 = __float2bfloat16(o3);
    size_t di = (size_t)i*2;
    ah[di]   = __nv_bfloat162(h0, h1);
    ah[di+1] = __nv_bfloat162(h2, h3);
    al[di]   = __nv_bfloat162(__float2bfloat16(o0 - __bfloat162float(h0)),
                              __float2bfloat16(o1 - __bfloat162float(h1)));
    al[di+1] = __nv_bfloat162(__float2bfloat16(o2 - __bfloat162float(h2)),
                              __float2bfloat16(o3 - __bfloat162float(h3)));
}

// ---------------- LayerNorm tap -> output (drop CLS token) ------------------
__global__ __launch_bounds__(256)
void ln_out(const float* __restrict__ h, const float* __restrict__ w,
            const float* __restrict__ b, float* __restrict__ o) {
    int br = blockIdx.x;
    int bb = br / NP_, n = br % NP_ + 1;
    const float* hr = h + (size_t)(bb*N_ + n)*E_;
    float* orow = o + (size_t)br*E_;
    __shared__ float red[256];
    int tid = threadIdx.x;
    float vv[3];
    float s = 0.f;
    #pragma unroll
    for (int t = 0; t < 3; t++) { vv[t] = hr[tid + t*256]; s += vv[t]; }
    red[tid] = s; __syncthreads();
    for (int st = 128; st > 0; st >>= 1) {
        if (tid < st) red[tid] += red[tid + st];
        __syncthreads();
    }
    float mean = red[0] * (1.0f/E_);
    __syncthreads();
    float s2 = 0.f;
    #pragma unroll
    for (int t = 0; t < 3; t++) { float dd = vv[t] - mean; s2 += dd*dd; }
    red[tid] = s2; __syncthreads();
    for (int st = 128; st > 0; st >>= 1) {
        if (tid < st) red[tid] += red[tid + st];
        __syncthreads();
    }
    float inv = rsqrtf(red[0]*(1.0f/E_) + 1e-6f);
    #pragma unroll
    for (int t = 0; t < 3; t++) {
        int e = tid + t*256;
        orow[e] = (vv[t] - mean)*inv*w[e] + b[e];
    }
}

// ======================= driver ==============================================
extern "C" void kernel_launch(void* const* d_in, const int* in_sizes, int n_in,
                              void* d_out, int out_size) {
    (void)in_sizes; (void)n_in; (void)out_size;
    const float* x       = (const float*)d_in[0];
    const float* patch_w = (const float*)d_in[1];
    const float* patch_b = (const float*)d_in[2];
    const float* cls     = (const float*)d_in[3];
    const float* pos     = (const float*)d_in[4];
    const float* Wq      = (const float*)d_in[5];
    const float* Wk      = (const float*)d_in[6];
    const float* Wv      = (const float*)d_in[7];
    const float* Wo      = (const float*)d_in[8];
    const float* s_qk    = (const float*)d_in[9];
    const float* Wup     = (const float*)d_in[10];
    const float* Wgate   = (const float*)d_in[11];
    const float* Wdown   = (const float*)d_in[12];
    const float* s_u     = (const float*)d_in[13];
    const float* s_v     = (const float*)d_in[14];
    const float* aA      = (const float*)d_in[15];
    const float* aM      = (const float*)d_in[16];
    const float* fcw     = (const float*)d_in[17];
    const float* fcb     = (const float*)d_in[18];
    float* out = (float*)d_out;

    float *h, *t, *qkv, *ug;
    __nv_bfloat16 *ah, *al, *wh, *wl;
    cudaGetSymbolAddress((void**)&h,   g_h);
    cudaGetSymbolAddress((void**)&t,   g_t);
    cudaGetSymbolAddress((void**)&qkv, g_qkv);
    cudaGetSymbolAddress((void**)&ug,  g_ug);
    cudaGetSymbolAddress((void**)&ah,  g_act_hi);
    cudaGetSymbolAddress((void**)&al,  g_act_lo);
    cudaGetSymbolAddress((void**)&wh,  g_w_hi);
    cudaGetSymbolAddress((void**)&wl,  g_w_lo);

    cudaFuncSetAttribute(gemm_mma, cudaFuncAttributeMaxDynamicSharedMemorySize, GSMEM);
    cudaFuncSetAttribute(attn_fused, cudaFuncAttributeMaxDynamicSharedMemorySize, ASMEM_BYTES);

    // weight split + repack (every call; deterministic); all counts /4
    cvt_pack4<<<(NQ_/4 +255)/256, 256>>>((const float4*)Wq, (__nv_bfloat162*)(wh+OFF_QKV),
        (__nv_bfloat162*)(wl+OFF_QKV), EE_/4, 3LL*EE_/2, NQ_/4);
    cvt_pack4<<<(NQ_/4 +255)/256, 256>>>((const float4*)Wk, (__nv_bfloat162*)(wh+OFF_QKV+EE_),
        (__nv_bfloat162*)(wl+OFF_QKV+EE_), EE_/4, 3LL*EE_/2, NQ_/4);
    cvt_pack4<<<(NQ_/4 +255)/256, 256>>>((const float4*)Wv, (__nv_bfloat162*)(wh+OFF_QKV+2*EE_),
        (__nv_bfloat162*)(wl+OFF_QKV+2*EE_), EE_/4, 3LL*EE_/2, NQ_/4);
    cvt_pack4<<<(NQ_/4 +255)/256, 256>>>((const float4*)Wo, (__nv_bfloat162*)(wh+OFF_O),
        (__nv_bfloat162*)(wl+OFF_O), EE_/4, (long long)EE_/2, NQ_/4);
    cvt_pack4<<<(NUP_/4+255)/256, 256>>>((const float4*)Wup, (__nv_bfloat162*)(wh+OFF_UG),
        (__nv_bfloat162*)(wl+OFF_UG), FFE_/4, 2LL*FFE_/2, NUP_/4);
    cvt_pack4<<<(NUP_/4+255)/256, 256>>>((const float4*)Wgate, (__nv_bfloat162*)(wh+OFF_UG+FFE_),
        (__nv_bfloat162*)(wl+OFF_UG+FFE_), FFE_/4, 2LL*FFE_/2, NUP_/4);
    cvt_pack4<<<(NUP_/4+255)/256, 256>>>((const float4*)Wdown, (__nv_bfloat162*)(wh+OFF_DOWN),
        (__nv_bfloat162*)(wl+OFF_DOWN), FFE_/4, (long long)FFE_/2, NUP_/4);

    patch_embed<<<B_*NP_, 256>>>(x, patch_w, patch_b, pos, h, ah, al);
    cls_pos<<<B_, 256>>>(cls, pos, h, ah, al);

    dim3 gQKV(3*E_/BN, (ROWS_ + BM - 1)/BM);  // (18, 25)
    dim3 gE(E_/BN, (ROWS_ + BM - 1)/BM);      // (6, 25)
    dim3 gUG(2*FF_/BN, (ROWS_ + BM - 1)/BM);  // (48, 25)
    const int nF4 = ROWS_*FF_/4;

    for (int l = 0; l < L_; l++) {
        const size_t oqkv = (size_t)l*3*EE_;
        const size_t oo   = (size_t)l*EE_;
        const size_t oug  = (size_t)l*2*FFE_;
        const size_t od   = (size_t)l*FFE_;
        gemm_mma<<<gQKV, 128, GSMEM>>>(ah, al, wh+OFF_QKV+oqkv, wl+OFF_QKV+oqkv,
                                       qkv, ROWS_, 3*E_, E_);
        attn_fused<<<B_*H_, 256, ASMEM_BYTES>>>(qkv, s_qk + (size_t)l*H_*HD_, ah, al);
        gemm_mma<<<gE, 128, GSMEM>>>(ah, al, wh+OFF_O+oo, wl+OFF_O+oo,
                                     t, ROWS_, E_, E_);
        res_cn<<<ROWS_, 256>>>(h, t, aA + (size_t)l*E_, ah, al);
        gemm_mma<<<gUG, 128, GSMEM>>>(ah, al, wh+OFF_UG+oug, wl+OFF_UG+oug,
                                      ug, ROWS_, 2*FF_, E_);
        mlp_act<<<(nF4 + 255)/256, 256>>>((const float4*)ug,
            (const float4*)(s_u + (size_t)l*FF_), (const float4*)(s_v + (size_t)l*FF_),
            (__nv_bfloat162*)ah, (__nv_bfloat162*)al);
        gemm_mma<<<gE, 128, GSMEM>>>(ah, al, wh+OFF_DOWN+od, wl+OFF_DOWN+od,
                                     t, ROWS_, E_, FF_);
        res_cn<<<ROWS_, 256>>>(h, t, aM + (size_t)l*E_, ah, al);
        if (l == L_ - 2)
            ln_out<<<B_*NP_, 256>>>(h, fcw, fcb, out);
    }
    ln_out<<<B_*NP_, 256>>>(h, fcw, fcb, out + (size_t)B_*NP_*E_);
}

// round 6
// speedup vs baseline: 3.4113x; 1.1148x over previous
#include <cuda_runtime.h>
#include <cuda_fp16.h>
#include <math.h>
#include <stdint.h>

#define B_   16
#define E_   768
#define H_   12
#define HD_  64
#define N_   197
#define NP_  196
#define L_   12
#define FF_  3072
#define ROWS_ (B_*N_)          // 3152
#define SQRTE 27.712812921102035f
#define EE_   (E_*E_)
#define FFE_  (FF_*E_)
#define LO_SCALE 4096.0f
#define LO_INV   (1.0f/4096.0f)

// packed fp16 weight layout: [QKV(3*NQ)] [O(NQ)] [UPGATE(2*NUP)] [DOWN(NUP)]
#define NQ_   (L_*EE_)
#define NUP_  (L_*FFE_)
#define OFF_QKV  0
#define OFF_O    (3*NQ_)
#define OFF_UG   (4*NQ_)
#define OFF_DOWN (4*NQ_ + 2*NUP_)
#define WTOT_    (4*NQ_ + 3*NUP_)

// ---------------- scratch (device globals; no allocation allowed) ----------
__device__ float g_h[ROWS_*E_];
__device__ float g_t[ROWS_*E_];
__device__ float g_qkv[ROWS_*3*E_];
__device__ float g_ug[ROWS_*2*FF_];
__device__ __half g_act_hi[ROWS_*FF_];
__device__ __half g_act_lo[ROWS_*FF_];
__device__ __half g_w[WTOT_];

// ======================= mma.sync GEMM ======================================
// C[M,N] = A[M,K] * W[N,K]^T ; A fp16 hi/lo (lo pre-scaled x4096), W fp16.
// D = Ah*W + (Al'*W)/4096.  8 warps, warp tile 64x32, CTA 128x128, 3 stages.
#define BM 128
#define BN 128
#define BK 32
#define PADE 40
#define ARR_BYTES (128*PADE*2)        // 10240
#define STAGE_BYTES (3*ARR_BYTES)     // 30720
#define GSMEM (3*STAGE_BYTES)         // 92160

__device__ __forceinline__ uint32_t smem_u32(const void* p) {
    uint32_t a;
    asm("{ .reg .u64 t; cvta.to.shared.u64 t, %1; cvt.u32.u64 %0, t; }"
        : "=r"(a) : "l"(p));
    return a;
}
__device__ __forceinline__ void cp16(uint32_t dst, const void* src) {
    asm volatile("cp.async.cg.shared.global [%0], [%1], 16;"
                 :: "r"(dst), "l"(src) : "memory");
}
#define CP_COMMIT() asm volatile("cp.async.commit_group;" ::: "memory")
#define CP_WAIT1()  asm volatile("cp.async.wait_group 1;" ::: "memory")

#define LDSM4(r, addr) \
    asm volatile("ldmatrix.sync.aligned.m8n8.x4.shared.b16 {%0,%1,%2,%3}, [%4];" \
        : "=r"((r)[0]), "=r"((r)[1]), "=r"((r)[2]), "=r"((r)[3]) : "r"(addr))
#define MMA_F16(d, a, b0, b1) \
    asm volatile("mma.sync.aligned.m16n8k16.row.col.f32.f16.f16.f32 " \
        "{%0,%1,%2,%3}, {%4,%5,%6,%7}, {%8,%9}, {%0,%1,%2,%3};" \
        : "+f"((d)[0]), "+f"((d)[1]), "+f"((d)[2]), "+f"((d)[3]) \
        : "r"((a)[0]), "r"((a)[1]), "r"((a)[2]), "r"((a)[3]), \
          "r"(b0), "r"(b1))

__device__ __forceinline__ void load_stage(
        uint32_t sbase,
        const __half* __restrict__ Ah, const __half* __restrict__ Al,
        const __half* __restrict__ W,
        int m0, int n0, int k0, int M, int K, int tid) {
    #pragma unroll
    for (int i = 0; i < 6; i++) {
        int idx = tid + i*256;                 // 1536 total
        int arr = idx >> 9;
        int rem = idx & 511;
        int row = rem >> 2;
        int seg = rem & 3;
        uint32_t dst = sbase + arr*ARR_BYTES + row*(PADE*2) + seg*16;
        const __half* src;
        if (arr == 0)      { int r = m0 + row; if (r >= M) r = M - 1;
                             src = Ah + (size_t)r*K + k0 + seg*8; }
        else if (arr == 1) { int r = m0 + row; if (r >= M) r = M - 1;
                             src = Al + (size_t)r*K + k0 + seg*8; }
        else               { src = W + (size_t)(n0 + row)*K + k0 + seg*8; }
        cp16(dst, src);
    }
}

__global__ __launch_bounds__(256)
void gemm_mma(const __half* __restrict__ Ah,
              const __half* __restrict__ Al,
              const __half* __restrict__ W,
              float* __restrict__ C, int M, int N, int K) {
    extern __shared__ char smem[];
    const uint32_t sb = smem_u32(smem);
    const int tid = threadIdx.x;
    const int lane = tid & 31, wid = tid >> 5;      // 8 warps
    const int wm = (wid & 1) * 64;
    const int wn = (wid >> 1) * 32;
    const int m0 = blockIdx.y * BM, n0 = blockIdx.x * BN;

    float accH[4][4][4] = {};
    float accL[4][4][4] = {};

    const int ntiles = K / BK;
    load_stage(sb,               Ah, Al, W, m0, n0, 0,  M, K, tid);
    CP_COMMIT();
    load_stage(sb + STAGE_BYTES, Ah, Al, W, m0, n0, BK, M, K, tid);
    CP_COMMIT();

    const int arow = lane & 15, acolsel = (lane >> 4) * 8;

    for (int t = 0; t < ntiles; t++) {
        CP_WAIT1();
        __syncthreads();
        if (t + 2 < ntiles)
            load_stage(sb + ((t + 2) % 3) * STAGE_BYTES,
                       Ah, Al, W, m0, n0, (t + 2) * BK, M, K, tid);
        CP_COMMIT();

        uint32_t sbase = sb + (t % 3) * STAGE_BYTES;
        const uint32_t sA_h = sbase;
        const uint32_t sA_l = sbase + ARR_BYTES;
        const uint32_t sW   = sbase + 2*ARR_BYTES;

        #pragma unroll
        for (int ks = 0; ks < 2; ks++) {
            const int kb = ks * 16;
            uint32_t ah[4][4], al[4][4], bw[2][4];
            #pragma unroll
            for (int mt = 0; mt < 4; mt++) {
                uint32_t off = (wm + mt*16 + arow)*(PADE*2) + (kb + acolsel)*2;
                LDSM4(ah[mt], sA_h + off);
                LDSM4(al[mt], sA_l + off);
            }
            #pragma unroll
            for (int nb = 0; nb < 2; nb++) {
                uint32_t off = (wn + nb*16 + arow)*(PADE*2) + (kb + acolsel)*2;
                LDSM4(bw[nb], sW + off);
            }
            #pragma unroll
            for (int mt = 0; mt < 4; mt++)
                #pragma unroll
                for (int nb = 0; nb < 2; nb++) {
                    MMA_F16(accH[mt][2*nb],   ah[mt], bw[nb][0], bw[nb][2]);
                    MMA_F16(accH[mt][2*nb+1], ah[mt], bw[nb][1], bw[nb][3]);
                    MMA_F16(accL[mt][2*nb],   al[mt], bw[nb][0], bw[nb][2]);
                    MMA_F16(accL[mt][2*nb+1], al[mt], bw[nb][1], bw[nb][3]);
                }
        }
        __syncthreads();
    }

    #pragma unroll
    for (int mt = 0; mt < 4; mt++) {
        int rbase = m0 + wm + mt*16 + (lane >> 2);
        #pragma unroll
        for (int half = 0; half < 2; half++) {
            int r = rbase + half*8;
            if (r < M) {
                float* crow = C + (size_t)r*N + n0 + wn + (lane & 3)*2;
                #pragma unroll
                for (int nt = 0; nt < 4; nt++) {
                    float2 v = make_float2(
                        accH[mt][nt][half*2]   + accL[mt][nt][half*2]  *LO_INV,
                        accH[mt][nt][half*2+1] + accL[mt][nt][half*2+1]*LO_INV);
                    *reinterpret_cast<float2*>(crow + nt*8) = v;
                }
            }
        }
    }
}

// ---------------- helpers: fp32 -> fp16 hi/lo (lo scaled) -------------------
__device__ __forceinline__ void split16(float x, __half& hi, __half& lo) {
    __half h = __float2half(x);
    hi = h;
    lo = __float2half((x - __half2float(h)) * LO_SCALE);
}

// ---------------- weight fp32 -> fp16, strided repack (x4 vector) -----------
__global__ void cvt_w4(const float4* __restrict__ src,
                       __half2* __restrict__ dst,
                       int chunk4, long long dst_stride2, int n4) {
    int i = blockIdx.x * blockDim.x + threadIdx.x;
    if (i >= n4) return;
    int l2 = i / chunk4, j = i - l2*chunk4;
    size_t di = (size_t)l2*dst_stride2 + (size_t)j*2;
    float4 x = src[i];
    dst[di]   = __half2(__float2half(x.x), __float2half(x.y));
    dst[di+1] = __half2(__float2half(x.z), __float2half(x.w));
}

// ---------------- patch embed (writes fp32 h + fp16 hi/lo) ------------------
__global__ void patch_embed(const float* __restrict__ x,
                            const float* __restrict__ pw,
                            const float* __restrict__ pb,
                            const float* __restrict__ pos,
                            float* __restrict__ h,
                            __half* __restrict__ ah,
                            __half* __restrict__ al) {
    int bp = blockIdx.x;
    int b = bp / NP_, pidx = bp % NP_;
    int gi = pidx / 14, gj = pidx % 14;
    __shared__ float patch[768];
    for (int i = threadIdx.x; i < 768; i += blockDim.x) {
        int c  = i >> 8;
        int r  = i & 255;
        int ii = r >> 4, jj = r & 15;
        patch[i] = x[((b*3 + c)*224 + gi*16 + ii)*224 + gj*16 + jj];
    }
    __syncthreads();
    for (int e = threadIdx.x; e < E_; e += blockDim.x) {
        const float* w = pw + e*768;
        float acc = 0.f;
        #pragma unroll 8
        for (int i = 0; i < 768; i++) acc = fmaf(patch[i], w[i], acc);
        float val = acc + pb[e] + pos[(1 + pidx)*E_ + e];
        size_t oi = (size_t)(b*N_ + 1 + pidx)*E_ + e;
        h[oi] = val;
        split16(val, ah[oi], al[oi]);
    }
}

__global__ void cls_pos(const float* __restrict__ cls,
                        const float* __restrict__ pos,
                        float* __restrict__ h,
                        __half* __restrict__ ah,
                        __half* __restrict__ al) {
    int b = blockIdx.x;
    for (int e = threadIdx.x; e < E_; e += blockDim.x) {
        float val = cls[e] + pos[e];
        size_t oi = (size_t)(b*N_)*E_ + e;
        h[oi] = val;
        split16(val, ah[oi], al[oi]);
    }
}

// ---------------- fused attention: one block per (b,h) ----------------------
#define AT_PAD 65
#define ASMEM_FLOATS (2*197*AT_PAD + 197 + 64 + 64 + 4*64 + 8 + 4)
#define ASMEM_BYTES  (ASMEM_FLOATS*4)

__global__ __launch_bounds__(256)
void attn_fused(const float* __restrict__ qkv,
                const float* __restrict__ s_qk,
                __half* __restrict__ ah,
                __half* __restrict__ al) {
    extern __shared__ float sm[];
    float* Ks = sm;
    float* Vs = Ks + 197*AT_PAD;
    float* lg = Vs + 197*AT_PAD;
    float* qs = lg + 197;
    float* ss = qs + 64;
    float* acc4 = ss + 64;
    float* red = acc4 + 256;
    float* invp = red + 8;

    int bh = blockIdx.x;
    int h = bh % H_, b = bh / H_;
    int tid = threadIdx.x, wid = tid >> 5, lane = tid & 31;
    const float* qb = qkv + (size_t)(b*N_)*(3*E_) + h*HD_;

    if (tid < 64) ss[tid] = s_qk[h*HD_ + tid] * SQRTE;
    for (int i = tid; i < 197*64; i += 256) {
        int m = i >> 6, d = i & 63;
        Ks[m*AT_PAD + d] = qb[(size_t)m*(3*E_) + E_ + d];
        Vs[m*AT_PAD + d] = qb[(size_t)m*(3*E_) + 2*E_ + d];
    }
    __syncthreads();
    for (int m = wid; m < N_; m += 8) {
        float v0 = Ks[m*AT_PAD + lane], v1 = Ks[m*AT_PAD + 32 + lane];
        float sq = v0*v0 + v1*v1;
        #pragma unroll
        for (int o = 16; o > 0; o >>= 1) sq += __shfl_xor_sync(~0u, sq, o);
        float inv = 1.f / fmaxf(sqrtf(sq), 1e-6f);
        Ks[m*AT_PAD + lane]      = v0 * inv * ss[lane];
        Ks[m*AT_PAD + 32 + lane] = v1 * inv * ss[lane + 32];
    }
    __syncthreads();

    for (int qn = 0; qn < N_; qn++) {
        if (wid == 0) {
            float v0 = qb[(size_t)qn*(3*E_) + lane];
            float v1 = qb[(size_t)qn*(3*E_) + 32 + lane];
            float sq = v0*v0 + v1*v1;
            #pragma unroll
            for (int o = 16; o > 0; o >>= 1) sq += __shfl_xor_sync(~0u, sq, o);
            float inv = 1.f / fmaxf(sqrtf(sq), 1e-6f);
            qs[lane]      = v0 * inv * ss[lane];
            qs[lane + 32] = v1 * inv * ss[lane + 32];
        }
        __syncthreads();
        float p = 0.f;
        if (tid < N_) {
            const float* kr = Ks + tid*AT_PAD;
            float sacc = 0.f;
            #pragma unroll
            for (int d = 0; d < 64; d++) sacc = fmaf(qs[d], kr[d], sacc);
            p = expf(sacc * 8.0f - 8.0f);
            lg[tid] = p;
        }
        float ws = p;
        #pragma unroll
        for (int o = 16; o > 0; o >>= 1) ws += __shfl_xor_sync(~0u, ws, o);
        if (lane == 0) red[wid] = ws;
        __syncthreads();
        if (tid == 0) {
            float s = 0.f;
            #pragma unroll
            for (int i = 0; i < 8; i++) s += red[i];
            invp[0] = 1.f / s;
        }
        int d = tid & 63, c = tid >> 6;
        float acc = 0.f;
        for (int m = c; m < N_; m += 4)
            acc = fmaf(lg[m], Vs[m*AT_PAD + d], acc);
        acc4[c*64 + d] = acc;
        __syncthreads();
        if (tid < 64) {
            float o2 = (acc4[tid] + acc4[64 + tid] + acc4[128 + tid] +
                        acc4[192 + tid]) * invp[0];
            size_t oi = ((size_t)(b*N_) + qn)*E_ + h*HD_ + tid;
            split16(o2, ah[oi], al[oi]);
        }
        __syncthreads();
    }
}

// ---------------- residual + double cosine-norm (+ fp16 split out) ----------
__global__ __launch_bounds__(256)
void res_cn(float* __restrict__ h, const float* __restrict__ d,
            const float* __restrict__ alpha,
            __half* __restrict__ ah, __half* __restrict__ al) {
    int row = blockIdx.x;
    int tid = threadIdx.x;
    const float* dr = d + (size_t)row*E_;
    float* hr = h + (size_t)row*E_;
    __shared__ float red[256];
    float dv[3], hv[3];
    float ss = 0.f;
    #pragma unroll
    for (int t = 0; t < 3; t++) {
        int e = tid + t*256;
        dv[t] = dr[e]; hv[t] = hr[e];
        ss += dv[t]*dv[t];
    }
    red[tid] = ss; __syncthreads();
    for (int s = 128; s > 0; s >>= 1) {
        if (tid < s) red[tid] += red[tid + s];
        __syncthreads();
    }
    float inv1 = 1.0f / fmaxf(sqrtf(red[0]), 1e-6f);
    __syncthreads();
    float y[3]; float ss2 = 0.f;
    #pragma unroll
    for (int t = 0; t < 3; t++) {
        int e = tid + t*256;
        float a = alpha[e] * (0.05f * SQRTE);
        y[t] = hv[t] + a*(dv[t]*inv1 - hv[t]);
        ss2 += y[t]*y[t];
    }
    red[tid] = ss2; __syncthreads();
    for (int s = 128; s > 0; s >>= 1) {
        if (tid < s) red[tid] += red[tid + s];
        __syncthreads();
    }
    float inv2 = 1.0f / fmaxf(sqrtf(red[0]), 1e-6f);
    #pragma unroll
    for (int t = 0; t < 3; t++) {
        int e = tid + t*256;
        float val = y[t]*inv2;
        hr[e] = val;
        size_t oi = (size_t)row*E_ + e;
        split16(val, ah[oi], al[oi]);
    }
}

// ---------------- MLP activation (packed ug -> fp16 hi/lo, x4 vector) -------
__global__ void mlp_act(const float4* __restrict__ ug,
                        const float4* __restrict__ s_u, const float4* __restrict__ s_v,
                        __half2* __restrict__ ah, __half2* __restrict__ al) {
    int i = blockIdx.x*blockDim.x + threadIdx.x;      // over ROWS_*FF_/4
    if (i >= ROWS_*FF_/4) return;
    int row = i / (FF_/4), j = i - row*(FF_/4);
    float4 uu = ug[(size_t)row*(2*FF_/4) + j];
    float4 vv = ug[(size_t)row*(2*FF_/4) + FF_/4 + j];
    float4 su = s_u[j], sv = s_v[j];
    float o0, o1, o2, o3;
    {
        float a = uu.x*su.x, b = vv.x*sv.x*SQRTE;
        o0 = a*b/(1.0f + expf(-b));
        a = uu.y*su.y; b = vv.y*sv.y*SQRTE;
        o1 = a*b/(1.0f + expf(-b));
        a = uu.z*su.z; b = vv.z*sv.z*SQRTE;
        o2 = a*b/(1.0f + expf(-b));
        a = uu.w*su.w; b = vv.w*sv.w*SQRTE;
        o3 = a*b/(1.0f + expf(-b));
    }
    __half h0, h1, h2, h3, l0, l1, l2, l3;
    split16(o0, h0, l0); split16(o1, h1, l1);
    split16(o2, h2, l2); split16(o3, h3, l3);
    size_t di = (size_t)i*2;
    ah[di]   = __half2(h0, h1);
    ah[di+1] = __half2(h2, h3);
    al[di]   = __half2(l0, l1);
    al[di+1] = __half2(l2, l3);
}

// ---------------- LayerNorm tap -> output (drop CLS token) ------------------
__global__ __launch_bounds__(256)
void ln_out(const float* __restrict__ h, const float* __restrict__ w,
            const float* __restrict__ b, float* __restrict__ o) {
    int br = blockIdx.x;
    int bb = br / NP_, n = br % NP_ + 1;
    const float* hr = h + (size_t)(bb*N_ + n)*E_;
    float* orow = o + (size_t)br*E_;
    __shared__ float red[256];
    int tid = threadIdx.x;
    float vv[3];
    float s = 0.f;
    #pragma unroll
    for (int t = 0; t < 3; t++) { vv[t] = hr[tid + t*256]; s += vv[t]; }
    red[tid] = s; __syncthreads();
    for (int st = 128; st > 0; st >>= 1) {
        if (tid < st) red[tid] += red[tid + st];
        __syncthreads();
    }
    float mean = red[0] * (1.0f/E_);
    __syncthreads();
    float s2 = 0.f;
    #pragma unroll
    for (int t = 0; t < 3; t++) { float dd = vv[t] - mean; s2 += dd*dd; }
    red[tid] = s2; __syncthreads();
    for (int st = 128; st > 0; st >>= 1) {
        if (tid < st) red[tid] += red[tid + st];
        __syncthreads();
    }
    float inv = rsqrtf(red[0]*(1.0f/E_) + 1e-6f);
    #pragma unroll
    for (int t = 0; t < 3; t++) {
        int e = tid + t*256;
        orow[e] = (vv[t] - mean)*inv*w[e] + b[e];
    }
}

// ======================= driver ==============================================
extern "C" void kernel_launch(void* const* d_in, const int* in_sizes, int n_in,
                              void* d_out, int out_size) {
    (void)in_sizes; (void)n_in; (void)out_size;
    const float* x       = (const float*)d_in[0];
    const float* patch_w = (const float*)d_in[1];
    const float* patch_b = (const float*)d_in[2];
    const float* cls     = (const float*)d_in[3];
    const float* pos     = (const float*)d_in[4];
    const float* Wq      = (const float*)d_in[5];
    const float* Wk      = (const float*)d_in[6];
    const float* Wv      = (const float*)d_in[7];
    const float* Wo      = (const float*)d_in[8];
    const float* s_qk    = (const float*)d_in[9];
    const float* Wup     = (const float*)d_in[10];
    const float* Wgate   = (const float*)d_in[11];
    const float* Wdown   = (const float*)d_in[12];
    const float* s_u     = (const float*)d_in[13];
    const float* s_v     = (const float*)d_in[14];
    const float* aA      = (const float*)d_in[15];
    const float* aM      = (const float*)d_in[16];
    const float* fcw     = (const float*)d_in[17];
    const float* fcb     = (const float*)d_in[18];
    float* out = (float*)d_out;

    float *h, *t, *qkv, *ug;
    __half *ah, *al, *wh;
    cudaGetSymbolAddress((void**)&h,   g_h);
    cudaGetSymbolAddress((void**)&t,   g_t);
    cudaGetSymbolAddress((void**)&qkv, g_qkv);
    cudaGetSymbolAddress((void**)&ug,  g_ug);
    cudaGetSymbolAddress((void**)&ah,  g_act_hi);
    cudaGetSymbolAddress((void**)&al,  g_act_lo);
    cudaGetSymbolAddress((void**)&wh,  g_w);

    cudaFuncSetAttribute(gemm_mma, cudaFuncAttributeMaxDynamicSharedMemorySize, GSMEM);
    cudaFuncSetAttribute(attn_fused, cudaFuncAttributeMaxDynamicSharedMemorySize, ASMEM_BYTES);

    // weight fp32 -> fp16, repacked (every call; deterministic)
    cvt_w4<<<(NQ_/4 +255)/256, 256>>>((const float4*)Wq, (__half2*)(wh+OFF_QKV),
        EE_/4, 3LL*EE_/2, NQ_/4);
    cvt_w4<<<(NQ_/4 +255)/256, 256>>>((const float4*)Wk, (__half2*)(wh+OFF_QKV+EE_),
        EE_/4, 3LL*EE_/2, NQ_/4);
    cvt_w4<<<(NQ_/4 +255)/256, 256>>>((const float4*)Wv, (__half2*)(wh+OFF_QKV+2*EE_),
        EE_/4, 3LL*EE_/2, NQ_/4);
    cvt_w4<<<(NQ_/4 +255)/256, 256>>>((const float4*)Wo, (__half2*)(wh+OFF_O),
        EE_/4, (long long)EE_/2, NQ_/4);
    cvt_w4<<<(NUP_/4+255)/256, 256>>>((const float4*)Wup, (__half2*)(wh+OFF_UG),
        FFE_/4, 2LL*FFE_/2, NUP_/4);
    cvt_w4<<<(NUP_/4+255)/256, 256>>>((const float4*)Wgate, (__half2*)(wh+OFF_UG+FFE_),
        FFE_/4, 2LL*FFE_/2, NUP_/4);
    cvt_w4<<<(NUP_/4+255)/256, 256>>>((const float4*)Wdown, (__half2*)(wh+OFF_DOWN),
        FFE_/4, (long long)FFE_/2, NUP_/4);

    patch_embed<<<B_*NP_, 256>>>(x, patch_w, patch_b, pos, h, ah, al);
    cls_pos<<<B_, 256>>>(cls, pos, h, ah, al);

    dim3 gQKV(3*E_/BN, (ROWS_ + BM - 1)/BM);  // (18, 25)
    dim3 gE(E_/BN, (ROWS_ + BM - 1)/BM);      // (6, 25)
    dim3 gUG(2*FF_/BN, (ROWS_ + BM - 1)/BM);  // (48, 25)
    const int nF4 = ROWS_*FF_/4;

    for (int l = 0; l < L_; l++) {
        const size_t oqkv = (size_t)l*3*EE_;
        const size_t oo   = (size_t)l*EE_;
        const size_t oug  = (size_t)l*2*FFE_;
        const size_t od   = (size_t)l*FFE_;
        gemm_mma<<<gQKV, 256, GSMEM>>>(ah, al, wh+OFF_QKV+oqkv,
                                       qkv, ROWS_, 3*E_, E_);
        attn_fused<<<B_*H_, 256, ASMEM_BYTES>>>(qkv, s_qk + (size_t)l*H_*HD_, ah, al);
        gemm_mma<<<gE, 256, GSMEM>>>(ah, al, wh+OFF_O+oo,
                                     t, ROWS_, E_, E_);
        res_cn<<<ROWS_, 256>>>(h, t, aA + (size_t)l*E_, ah, al);
        gemm_mma<<<gUG, 256, GSMEM>>>(ah, al, wh+OFF_UG+oug,
                                      ug, ROWS_, 2*FF_, E_);
        mlp_act<<<(nF4 + 255)/256, 256>>>((const float4*)ug,
            (const float4*)(s_u + (size_t)l*FF_), (const float4*)(s_v + (size_t)l*FF_),
            (__half2*)ah, (__half2*)al);
        gemm_mma<<<gE, 256, GSMEM>>>(ah, al, wh+OFF_DOWN+od,
                                     t, ROWS_, E_, FF_);
        res_cn<<<ROWS_, 256>>>(h, t, aM + (size_t)l*E_, ah, al);
        if (l == L_ - 2)
            ln_out<<<B_*NP_, 256>>>(h, fcw, fcb, out);
    }
    ln_out<<<B_*NP_, 256>>>(h, fcw, fcb, out + (size_t)B_*NP_*E_);
}

// round 7
// speedup vs baseline: 4.0123x; 1.1762x over previous
#include <cuda_runtime.h>
#include <cuda_fp16.h>
#include <math.h>
#include <stdint.h>

#define B_   16
#define E_   768
#define H_   12
#define HD_  64
#define N_   197
#define NP_  196
#define L_   12
#define FF_  3072
#define ROWS_ (B_*N_)          // 3152
#define SQRTE 27.712812921102035f
#define EE_   (E_*E_)
#define FFE_  (FF_*E_)

// packed fp16 weight layout: [QKV(3*NQ)] [O(NQ)] [UPGATE(2*NUP)] [DOWN(NUP)]
#define NQ_   (L_*EE_)
#define NUP_  (L_*FFE_)
#define OFF_QKV  0
#define OFF_O    (3*NQ_)
#define OFF_UG   (4*NQ_)
#define OFF_DOWN (4*NQ_ + 2*NUP_)
#define WTOT_    (4*NQ_ + 3*NUP_)

// ---------------- scratch (device globals; no allocation allowed) ----------
__device__ float g_h[ROWS_*E_];
__device__ float g_t[ROWS_*E_];
__device__ float g_qkv[ROWS_*3*E_];
__device__ float g_ug[ROWS_*2*FF_];
__device__ __half g_act[ROWS_*FF_];
__device__ __half g_w[WTOT_];

// ======================= mma.sync GEMM ======================================
// C[M,N] = A[M,K] * W[N,K]^T ; A,W fp16, fp32 accum. 8 warps, warp 64x32,
// CTA 128x128, BK=32, 4-stage cp.async pipeline, 2 CTAs/SM.
#define BM 128
#define BN 128
#define BK 32
#define PADE 40
#define ARR_BYTES (128*PADE*2)        // 10240
#define STAGE_BYTES (2*ARR_BYTES)     // 20480
#define NSTAGE 4
#define GSMEM (NSTAGE*STAGE_BYTES)    // 81920

__device__ __forceinline__ uint32_t smem_u32(const void* p) {
    uint32_t a;
    asm("{ .reg .u64 t; cvta.to.shared.u64 t, %1; cvt.u32.u64 %0, t; }"
        : "=r"(a) : "l"(p));
    return a;
}
__device__ __forceinline__ void cp16(uint32_t dst, const void* src) {
    asm volatile("cp.async.cg.shared.global [%0], [%1], 16;"
                 :: "r"(dst), "l"(src) : "memory");
}
#define CP_COMMIT() asm volatile("cp.async.commit_group;" ::: "memory")
#define CP_WAIT2()  asm volatile("cp.async.wait_group 2;" ::: "memory")

#define LDSM4(r, addr) \
    asm volatile("ldmatrix.sync.aligned.m8n8.x4.shared.b16 {%0,%1,%2,%3}, [%4];" \
        : "=r"((r)[0]), "=r"((r)[1]), "=r"((r)[2]), "=r"((r)[3]) : "r"(addr))
#define MMA_F16(d, a, b0, b1) \
    asm volatile("mma.sync.aligned.m16n8k16.row.col.f32.f16.f16.f32 " \
        "{%0,%1,%2,%3}, {%4,%5,%6,%7}, {%8,%9}, {%0,%1,%2,%3};" \
        : "+f"((d)[0]), "+f"((d)[1]), "+f"((d)[2]), "+f"((d)[3]) \
        : "r"((a)[0]), "r"((a)[1]), "r"((a)[2]), "r"((a)[3]), \
          "r"(b0), "r"(b1))

__device__ __forceinline__ void load_stage(
        uint32_t sbase,
        const __half* __restrict__ A, const __half* __restrict__ W,
        int m0, int n0, int k0, int M, int K, int tid) {
    #pragma unroll
    for (int i = 0; i < 4; i++) {
        int idx = tid + i*256;                 // 1024 total
        int arr = idx >> 9;
        int rem = idx & 511;
        int row = rem >> 2;
        int seg = rem & 3;
        uint32_t dst = sbase + arr*ARR_BYTES + row*(PADE*2) + seg*16;
        const __half* src;
        if (arr == 0) { int r = m0 + row; if (r >= M) r = M - 1;
                        src = A + (size_t)r*K + k0 + seg*8; }
        else          { src = W + (size_t)(n0 + row)*K + k0 + seg*8; }
        cp16(dst, src);
    }
}

__global__ __launch_bounds__(256, 2)
void gemm_mma(const __half* __restrict__ A,
              const __half* __restrict__ W,
              float* __restrict__ C, int M, int N, int K) {
    extern __shared__ char smem[];
    const uint32_t sb = smem_u32(smem);
    const int tid = threadIdx.x;
    const int lane = tid & 31, wid = tid >> 5;      // 8 warps
    const int wm = (wid & 1) * 64;
    const int wn = (wid >> 1) * 32;
    const int m0 = blockIdx.y * BM, n0 = blockIdx.x * BN;

    float acc[4][4][4] = {};

    const int ntiles = K / BK;
    load_stage(sb,                 A, W, m0, n0, 0,    M, K, tid);
    CP_COMMIT();
    load_stage(sb + STAGE_BYTES,   A, W, m0, n0, BK,   M, K, tid);
    CP_COMMIT();
    load_stage(sb + 2*STAGE_BYTES, A, W, m0, n0, 2*BK, M, K, tid);
    CP_COMMIT();

    const int arow = lane & 15, acolsel = (lane >> 4) * 8;

    for (int t = 0; t < ntiles; t++) {
        CP_WAIT2();
        __syncthreads();
        if (t + 3 < ntiles)
            load_stage(sb + ((t + 3) % NSTAGE) * STAGE_BYTES,
                       A, W, m0, n0, (t + 3) * BK, M, K, tid);
        CP_COMMIT();

        uint32_t sbase = sb + (t % NSTAGE) * STAGE_BYTES;
        const uint32_t sA = sbase;
        const uint32_t sW = sbase + ARR_BYTES;

        #pragma unroll
        for (int ks = 0; ks < 2; ks++) {
            const int kb = ks * 16;
            uint32_t ar[4][4], bw[2][4];
            #pragma unroll
            for (int mt = 0; mt < 4; mt++) {
                uint32_t off = (wm + mt*16 + arow)*(PADE*2) + (kb + acolsel)*2;
                LDSM4(ar[mt], sA + off);
            }
            #pragma unroll
            for (int nb = 0; nb < 2; nb++) {
                uint32_t off = (wn + nb*16 + arow)*(PADE*2) + (kb + acolsel)*2;
                LDSM4(bw[nb], sW + off);
            }
            #pragma unroll
            for (int mt = 0; mt < 4; mt++)
                #pragma unroll
                for (int nb = 0; nb < 2; nb++) {
                    MMA_F16(acc[mt][2*nb],   ar[mt], bw[nb][0], bw[nb][2]);
                    MMA_F16(acc[mt][2*nb+1], ar[mt], bw[nb][1], bw[nb][3]);
                }
        }
        __syncthreads();
    }

    #pragma unroll
    for (int mt = 0; mt < 4; mt++) {
        int rbase = m0 + wm + mt*16 + (lane >> 2);
        #pragma unroll
        for (int half = 0; half < 2; half++) {
            int r = rbase + half*8;
            if (r < M) {
                float* crow = C + (size_t)r*N + n0 + wn + (lane & 3)*2;
                #pragma unroll
                for (int nt = 0; nt < 4; nt++) {
                    float2 v = make_float2(acc[mt][nt][half*2],
                                           acc[mt][nt][half*2 + 1]);
                    *reinterpret_cast<float2*>(crow + nt*8) = v;
                }
            }
        }
    }
}

// ---------------- weight fp32 -> fp16, strided repack (x4 vector) -----------
__global__ void cvt_w4(const float4* __restrict__ src,
                       __half2* __restrict__ dst,
                       int chunk4, long long dst_stride2, int n4) {
    int i = blockIdx.x * blockDim.x + threadIdx.x;
    if (i >= n4) return;
    int l2 = i / chunk4, j = i - l2*chunk4;
    size_t di = (size_t)l2*dst_stride2 + (size_t)j*2;
    float4 x = src[i];
    dst[di]   = __half2(__float2half(x.x), __float2half(x.y));
    dst[di+1] = __half2(__float2half(x.z), __float2half(x.w));
}

// ---------------- patch embed (writes fp32 h + fp16 act) --------------------
__global__ void patch_embed(const float* __restrict__ x,
                            const float* __restrict__ pw,
                            const float* __restrict__ pb,
                            const float* __restrict__ pos,
                            float* __restrict__ h,
                            __half* __restrict__ ah) {
    int bp = blockIdx.x;
    int b = bp / NP_, pidx = bp % NP_;
    int gi = pidx / 14, gj = pidx % 14;
    __shared__ float patch[768];
    for (int i = threadIdx.x; i < 768; i += blockDim.x) {
        int c  = i >> 8;
        int r  = i & 255;
        int ii = r >> 4, jj = r & 15;
        patch[i] = x[((b*3 + c)*224 + gi*16 + ii)*224 + gj*16 + jj];
    }
    __syncthreads();
    for (int e = threadIdx.x; e < E_; e += blockDim.x) {
        const float* w = pw + e*768;
        float acc = 0.f;
        #pragma unroll 8
        for (int i = 0; i < 768; i++) acc = fmaf(patch[i], w[i], acc);
        float val = acc + pb[e] + pos[(1 + pidx)*E_ + e];
        size_t oi = (size_t)(b*N_ + 1 + pidx)*E_ + e;
        h[oi] = val;
        ah[oi] = __float2half(val);
    }
}

__global__ void cls_pos(const float* __restrict__ cls,
                        const float* __restrict__ pos,
                        float* __restrict__ h,
                        __half* __restrict__ ah) {
    int b = blockIdx.x;
    for (int e = threadIdx.x; e < E_; e += blockDim.x) {
        float val = cls[e] + pos[e];
        size_t oi = (size_t)(b*N_)*E_ + e;
        h[oi] = val;
        ah[oi] = __float2half(val);
    }
}

// ---------------- fused attention: one block per (b,h) ----------------------
#define AT_PAD 65
#define ASMEM_FLOATS (2*197*AT_PAD + 197 + 64 + 64 + 4*64 + 8 + 4)
#define ASMEM_BYTES  (ASMEM_FLOATS*4)

__global__ __launch_bounds__(256)
void attn_fused(const float* __restrict__ qkv,
                const float* __restrict__ s_qk,
                __half* __restrict__ ah) {
    extern __shared__ float sm[];
    float* Ks = sm;
    float* Vs = Ks + 197*AT_PAD;
    float* lg = Vs + 197*AT_PAD;
    float* qs = lg + 197;
    float* ss = qs + 64;
    float* acc4 = ss + 64;
    float* red = acc4 + 256;
    float* invp = red + 8;

    int bh = blockIdx.x;
    int h = bh % H_, b = bh / H_;
    int tid = threadIdx.x, wid = tid >> 5, lane = tid & 31;
    const float* qb = qkv + (size_t)(b*N_)*(3*E_) + h*HD_;

    if (tid < 64) ss[tid] = s_qk[h*HD_ + tid] * SQRTE;
    for (int i = tid; i < 197*64; i += 256) {
        int m = i >> 6, d = i & 63;
        Ks[m*AT_PAD + d] = qb[(size_t)m*(3*E_) + E_ + d];
        Vs[m*AT_PAD + d] = qb[(size_t)m*(3*E_) + 2*E_ + d];
    }
    __syncthreads();
    for (int m = wid; m < N_; m += 8) {
        float v0 = Ks[m*AT_PAD + lane], v1 = Ks[m*AT_PAD + 32 + lane];
        float sq = v0*v0 + v1*v1;
        #pragma unroll
        for (int o = 16; o > 0; o >>= 1) sq += __shfl_xor_sync(~0u, sq, o);
        float inv = 1.f / fmaxf(sqrtf(sq), 1e-6f);
        Ks[m*AT_PAD + lane]      = v0 * inv * ss[lane];
        Ks[m*AT_PAD + 32 + lane] = v1 * inv * ss[lane + 32];
    }
    __syncthreads();

    for (int qn = 0; qn < N_; qn++) {
        if (wid == 0) {
            float v0 = qb[(size_t)qn*(3*E_) + lane];
            float v1 = qb[(size_t)qn*(3*E_) + 32 + lane];
            float sq = v0*v0 + v1*v1;
            #pragma unroll
            for (int o = 16; o > 0; o >>= 1) sq += __shfl_xor_sync(~0u, sq, o);
            float inv = 1.f / fmaxf(sqrtf(sq), 1e-6f);
            qs[lane]      = v0 * inv * ss[lane];
            qs[lane + 32] = v1 * inv * ss[lane + 32];
        }
        __syncthreads();
        float p = 0.f;
        if (tid < N_) {
            const float* kr = Ks + tid*AT_PAD;
            float sacc = 0.f;
            #pragma unroll
            for (int d = 0; d < 64; d++) sacc = fmaf(qs[d], kr[d], sacc);
            p = expf(sacc * 8.0f - 8.0f);
            lg[tid] = p;
        }
        float ws = p;
        #pragma unroll
        for (int o = 16; o > 0; o >>= 1) ws += __shfl_xor_sync(~0u, ws, o);
        if (lane == 0) red[wid] = ws;
        __syncthreads();
        if (tid == 0) {
            float s = 0.f;
            #pragma unroll
            for (int i = 0; i < 8; i++) s += red[i];
            invp[0] = 1.f / s;
        }
        int d = tid & 63, c = tid >> 6;
        float acc = 0.f;
        for (int m = c; m < N_; m += 4)
            acc = fmaf(lg[m], Vs[m*AT_PAD + d], acc);
        acc4[c*64 + d] = acc;
        __syncthreads();
        if (tid < 64) {
            float o2 = (acc4[tid] + acc4[64 + tid] + acc4[128 + tid] +
                        acc4[192 + tid]) * invp[0];
            size_t oi = ((size_t)(b*N_) + qn)*E_ + h*HD_ + tid;
            ah[oi] = __float2half(o2);
        }
        __syncthreads();
    }
}

// ---------------- residual + double cosine-norm (+ fp16 out) ----------------
__global__ __launch_bounds__(256)
void res_cn(float* __restrict__ h, const float* __restrict__ d,
            const float* __restrict__ alpha,
            __half* __restrict__ ah) {
    int row = blockIdx.x;
    int tid = threadIdx.x;
    const float* dr = d + (size_t)row*E_;
    float* hr = h + (size_t)row*E_;
    __shared__ float red[256];
    float dv[3], hv[3];
    float ss = 0.f;
    #pragma unroll
    for (int t = 0; t < 3; t++) {
        int e = tid + t*256;
        dv[t] = dr[e]; hv[t] = hr[e];
        ss += dv[t]*dv[t];
    }
    red[tid] = ss; __syncthreads();
    for (int s = 128; s > 0; s >>= 1) {
        if (tid < s) red[tid] += red[tid + s];
        __syncthreads();
    }
    float inv1 = 1.0f / fmaxf(sqrtf(red[0]), 1e-6f);
    __syncthreads();
    float y[3]; float ss2 = 0.f;
    #pragma unroll
    for (int t = 0; t < 3; t++) {
        int e = tid + t*256;
        float a = alpha[e] * (0.05f * SQRTE);
        y[t] = hv[t] + a*(dv[t]*inv1 - hv[t]);
        ss2 += y[t]*y[t];
    }
    red[tid] = ss2; __syncthreads();
    for (int s = 128; s > 0; s >>= 1) {
        if (tid < s) red[tid] += red[tid + s];
        __syncthreads();
    }
    float inv2 = 1.0f / fmaxf(sqrtf(red[0]), 1e-6f);
    #pragma unroll
    for (int t = 0; t < 3; t++) {
        int e = tid + t*256;
        float val = y[t]*inv2;
        hr[e] = val;
        ah[(size_t)row*E_ + e] = __float2half(val);
    }
}

// ---------------- MLP activation (packed ug -> fp16, x4 vector) -------------
__global__ void mlp_act(const float4* __restrict__ ug,
                        const float4* __restrict__ s_u, const float4* __restrict__ s_v,
                        __half2* __restrict__ ah) {
    int i = blockIdx.x*blockDim.x + threadIdx.x;      // over ROWS_*FF_/4
    if (i >= ROWS_*FF_/4) return;
    int row = i / (FF_/4), j = i - row*(FF_/4);
    float4 uu = ug[(size_t)row*(2*FF_/4) + j];
    float4 vv = ug[(size_t)row*(2*FF_/4) + FF_/4 + j];
    float4 su = s_u[j], sv = s_v[j];
    float o0, o1, o2, o3;
    {
        float a = uu.x*su.x, b = vv.x*sv.x*SQRTE;
        o0 = a*b/(1.0f + expf(-b));
        a = uu.y*su.y; b = vv.y*sv.y*SQRTE;
        o1 = a*b/(1.0f + expf(-b));
        a = uu.z*su.z; b = vv.z*sv.z*SQRTE;
        o2 = a*b/(1.0f + expf(-b));
        a = uu.w*su.w; b = vv.w*sv.w*SQRTE;
        o3 = a*b/(1.0f + expf(-b));
    }
    size_t di = (size_t)i*2;
    ah[di]   = __half2(__float2half(o0), __float2half(o1));
    ah[di+1] = __half2(__float2half(o2), __float2half(o3));
}

// ---------------- LayerNorm tap -> output (drop CLS token) ------------------
__global__ __launch_bounds__(256)
void ln_out(const float* __restrict__ h, const float* __restrict__ w,
            const float* __restrict__ b, float* __restrict__ o) {
    int br = blockIdx.x;
    int bb = br / NP_, n = br % NP_ + 1;
    const float* hr = h + (size_t)(bb*N_ + n)*E_;
    float* orow = o + (size_t)br*E_;
    __shared__ float red[256];
    int tid = threadIdx.x;
    float vv[3];
    float s = 0.f;
    #pragma unroll
    for (int t = 0; t < 3; t++) { vv[t] = hr[tid + t*256]; s += vv[t]; }
    red[tid] = s; __syncthreads();
    for (int st = 128; st > 0; st >>= 1) {
        if (tid < st) red[tid] += red[tid + st];
        __syncthreads();
    }
    float mean = red[0] * (1.0f/E_);
    __syncthreads();
    float s2 = 0.f;
    #pragma unroll
    for (int t = 0; t < 3; t++) { float dd = vv[t] - mean; s2 += dd*dd; }
    red[tid] = s2; __syncthreads();
    for (int st = 128; st > 0; st >>= 1) {
        if (tid < st) red[tid] += red[tid + st];
        __syncthreads();
    }
    float inv = rsqrtf(red[0]*(1.0f/E_) + 1e-6f);
    #pragma unroll
    for (int t = 0; t < 3; t++) {
        int e = tid + t*256;
        orow[e] = (vv[t] - mean)*inv*w[e] + b[e];
    }
}

// ======================= driver ==============================================
extern "C" void kernel_launch(void* const* d_in, const int* in_sizes, int n_in,
                              void* d_out, int out_size) {
    (void)in_sizes; (void)n_in; (void)out_size;
    const float* x       = (const float*)d_in[0];
    const float* patch_w = (const float*)d_in[1];
    const float* patch_b = (const float*)d_in[2];
    const float* cls     = (const float*)d_in[3];
    const float* pos     = (const float*)d_in[4];
    const float* Wq      = (const float*)d_in[5];
    const float* Wk      = (const float*)d_in[6];
    const float* Wv      = (const float*)d_in[7];
    const float* Wo      = (const float*)d_in[8];
    const float* s_qk    = (const float*)d_in[9];
    const float* Wup     = (const float*)d_in[10];
    const float* Wgate   = (const float*)d_in[11];
    const float* Wdown   = (const float*)d_in[12];
    const float* s_u     = (const float*)d_in[13];
    const float* s_v     = (const float*)d_in[14];
    const float* aA      = (const float*)d_in[15];
    const float* aM      = (const float*)d_in[16];
    const float* fcw     = (const float*)d_in[17];
    const float* fcb     = (const float*)d_in[18];
    float* out = (float*)d_out;

    float *h, *t, *qkv, *ug;
    __half *ah, *wh;
    cudaGetSymbolAddress((void**)&h,   g_h);
    cudaGetSymbolAddress((void**)&t,   g_t);
    cudaGetSymbolAddress((void**)&qkv, g_qkv);
    cudaGetSymbolAddress((void**)&ug,  g_ug);
    cudaGetSymbolAddress((void**)&ah,  g_act);
    cudaGetSymbolAddress((void**)&wh,  g_w);

    cudaFuncSetAttribute(gemm_mma, cudaFuncAttributeMaxDynamicSharedMemorySize, GSMEM);
    cudaFuncSetAttribute(attn_fused, cudaFuncAttributeMaxDynamicSharedMemorySize, ASMEM_BYTES);

    // weight fp32 -> fp16, repacked (every call; deterministic)
    cvt_w4<<<(NQ_/4 +255)/256, 256>>>((const float4*)Wq, (__half2*)(wh+OFF_QKV),
        EE_/4, 3LL*EE_/2, NQ_/4);
    cvt_w4<<<(NQ_/4 +255)/256, 256>>>((const float4*)Wk, (__half2*)(wh+OFF_QKV+EE_),
        EE_/4, 3LL*EE_/2, NQ_/4);
    cvt_w4<<<(NQ_/4 +255)/256, 256>>>((const float4*)Wv, (__half2*)(wh+OFF_QKV+2*EE_),
        EE_/4, 3LL*EE_/2, NQ_/4);
    cvt_w4<<<(NQ_/4 +255)/256, 256>>>((const float4*)Wo, (__half2*)(wh+OFF_O),
        EE_/4, (long long)EE_/2, NQ_/4);
    cvt_w4<<<(NUP_/4+255)/256, 256>>>((const float4*)Wup, (__half2*)(wh+OFF_UG),
        FFE_/4, 2LL*FFE_/2, NUP_/4);
    cvt_w4<<<(NUP_/4+255)/256, 256>>>((const float4*)Wgate, (__half2*)(wh+OFF_UG+FFE_),
        FFE_/4, 2LL*FFE_/2, NUP_/4);
    cvt_w4<<<(NUP_/4+255)/256, 256>>>((const float4*)Wdown, (__half2*)(wh+OFF_DOWN),
        FFE_/4, (long long)FFE_/2, NUP_/4);

    patch_embed<<<B_*NP_, 256>>>(x, patch_w, patch_b, pos, h, ah);
    cls_pos<<<B_, 256>>>(cls, pos, h, ah);

    dim3 gQKV(3*E_/BN, (ROWS_ + BM - 1)/BM);  // (18, 25)
    dim3 gE(E_/BN, (ROWS_ + BM - 1)/BM);      // (6, 25)
    dim3 gUG(2*FF_/BN, (ROWS_ + BM - 1)/BM);  // (48, 25)
    const int nF4 = ROWS_*FF_/4;

    for (int l = 0; l < L_; l++) {
        const size_t oqkv = (size_t)l*3*EE_;
        const size_t oo   = (size_t)l*EE_;
        const size_t oug  = (size_t)l*2*FFE_;
        const size_t od   = (size_t)l*FFE_;
        gemm_mma<<<gQKV, 256, GSMEM>>>(ah, wh+OFF_QKV+oqkv, qkv, ROWS_, 3*E_, E_);
        attn_fused<<<B_*H_, 256, ASMEM_BYTES>>>(qkv, s_qk + (size_t)l*H_*HD_, ah);
        gemm_mma<<<gE, 256, GSMEM>>>(ah, wh+OFF_O+oo, t, ROWS_, E_, E_);
        res_cn<<<ROWS_, 256>>>(h, t, aA + (size_t)l*E_, ah);
        gemm_mma<<<gUG, 256, GSMEM>>>(ah, wh+OFF_UG+oug, ug, ROWS_, 2*FF_, E_);
        mlp_act<<<(nF4 + 255)/256, 256>>>((const float4*)ug,
            (const float4*)(s_u + (size_t)l*FF_), (const float4*)(s_v + (size_t)l*FF_),
            (__half2*)ah);
        gemm_mma<<<gE, 256, GSMEM>>>(ah, wh+OFF_DOWN+od, t, ROWS_, E_, FF_);
        res_cn<<<ROWS_, 256>>>(h, t, aM + (size_t)l*E_, ah);
        if (l == L_ - 2)
            ln_out<<<B_*NP_, 256>>>(h, fcw, fcb, out);
    }
    ln_out<<<B_*NP_, 256>>>(h, fcw, fcb, out + (size_t)B_*NP_*E_);
}